// round 1
// baseline (speedup 1.0000x reference)
#include <cuda_runtime.h>
#include <math.h>

// Problem constants
#define BB 4
#define SS 2048
#define DD 1024
#define HH 16
#define DH 64
#define MM (BB * SS)   // 8192

// ---------------------------------------------------------------------------
// Scratch (device globals; allocation inside kernel_launch is forbidden)
// ---------------------------------------------------------------------------
__device__ float g_Qh[(size_t)MM * DD];
__device__ float g_Kh[(size_t)MM * DD];
__device__ float g_Vh[(size_t)MM * DD];
__device__ float g_Ctx[(size_t)MM * DD];

// ---------------------------------------------------------------------------
// GEMM: C[m,n] = sum_k A[m,k] * W[n,k] + bias[n]
// A: [MM, 1024] row-major, W: [1024, 1024] row-major (torch Linear weight)
// Tile: 64(M) x 128(N) x 16(K), 256 threads, 4x8 micro-tile per thread.
// ---------------------------------------------------------------------------
#define GBM 64
#define GBN 128
#define GBK 16
#define GPAD 4

__global__ __launch_bounds__(256) void gemm_nt_bias(
    const float* __restrict__ A, const float* __restrict__ W,
    const float* __restrict__ bias, float* __restrict__ C)
{
    __shared__ float As[GBK][GBM + GPAD];   // [k][m]
    __shared__ float Bs[GBK][GBN + GPAD];   // [k][n]

    const int tid = threadIdx.x;
    const int tr  = tid >> 4;    // 0..15  (row group)
    const int tc  = tid & 15;    // 0..15  (col group)
    const int m0  = blockIdx.y * GBM;
    const int n0  = blockIdx.x * GBN;

    const float* Ab = A + (size_t)m0 * DD;
    const float* Wb = W + (size_t)n0 * DD;

    float acc[4][8];
#pragma unroll
    for (int i = 0; i < 4; i++)
#pragma unroll
        for (int j = 0; j < 8; j++) acc[i][j] = 0.0f;

    for (int k0 = 0; k0 < DD; k0 += GBK) {
        // Load A tile 64x16 -> As[k][m]
#pragma unroll
        for (int i = tid; i < GBM * GBK; i += 256) {
            int r = i >> 4, c = i & 15;
            As[c][r] = Ab[r * DD + k0 + c];
        }
        // Load W tile 128x16 -> Bs[k][n]
#pragma unroll
        for (int i = tid; i < GBN * GBK; i += 256) {
            int r = i >> 4, c = i & 15;
            Bs[c][r] = Wb[r * DD + k0 + c];
        }
        __syncthreads();

#pragma unroll
        for (int k = 0; k < GBK; k++) {
            float4 a4 = *(const float4*)&As[k][tr * 4];
            float4 b0 = *(const float4*)&Bs[k][tc * 8];
            float4 b1 = *(const float4*)&Bs[k][tc * 8 + 4];
            float a[4] = {a4.x, a4.y, a4.z, a4.w};
            float b[8] = {b0.x, b0.y, b0.z, b0.w, b1.x, b1.y, b1.z, b1.w};
#pragma unroll
            for (int i = 0; i < 4; i++)
#pragma unroll
                for (int j = 0; j < 8; j++)
                    acc[i][j] += a[i] * b[j];
        }
        __syncthreads();
    }

#pragma unroll
    for (int i = 0; i < 4; i++) {
        int row = m0 + tr * 4 + i;
#pragma unroll
        for (int j = 0; j < 8; j++) {
            int col = n0 + tc * 8 + j;
            C[(size_t)row * DD + col] = acc[i][j] + bias[col];
        }
    }
}

// ---------------------------------------------------------------------------
// Causal flash attention, fp32.
// Grid: (S/64, H, B). Block: 256 threads. Tile 64(q) x 64(k), DH = 64.
// smem: Qs [dh][r], KPs [dh][c] (reused as P^T [c][r]), Vs [c][dh], pad 68.
// ---------------------------------------------------------------------------
#define FST 68
#define FLASH_SMEM (3 * 64 * FST * (int)sizeof(float))  // 52224 bytes

__global__ __launch_bounds__(256) void flash_attn(
    const float* __restrict__ Q, const float* __restrict__ K,
    const float* __restrict__ V, float* __restrict__ O)
{
    extern __shared__ float sm[];
    float* Qs  = sm;                 // [64][FST] as [dh][r]
    float* KPs = sm + 64 * FST;      // [dh][c] for scores, then [c][r] for P
    float* Vs  = sm + 2 * 64 * FST;  // [c][dh]

    const int tid = threadIdx.x;
    const int tr  = tid >> 4;   // 0..15: owns q-rows tr*4 .. tr*4+3
    const int tc  = tid & 15;   // 0..15: owns cols  tc*4 .. tc*4+3
    const int qt  = blockIdx.x;
    const int h   = blockIdx.y;
    const int b   = blockIdx.z;
    const int s0  = qt * 64;

    const size_t base = ((size_t)b * SS) * DD + h * DH;

    // Load Q tile (pre-scaled by 1/sqrt(DH)), transposed to [dh][r]
#pragma unroll
    for (int i = tid; i < 64 * 64; i += 256) {
        int r = i >> 6, d = i & 63;
        Qs[d * FST + r] = Q[base + (size_t)(s0 + r) * DD + d] * 0.125f;
    }

    float o[4][4];
    float mrun[4], lrun[4];
#pragma unroll
    for (int i = 0; i < 4; i++) {
        mrun[i] = -1e30f;
        lrun[i] = 0.0f;
#pragma unroll
        for (int j = 0; j < 4; j++) o[i][j] = 0.0f;
    }
    __syncthreads();

    for (int kt = 0; kt <= qt; kt++) {
        const int c0 = kt * 64;
        // Load K (transposed -> [dh][c]) and V (natural -> [c][dh])
#pragma unroll
        for (int i = tid; i < 64 * 64; i += 256) {
            int r = i >> 6, d = i & 63;
            size_t g = base + (size_t)(c0 + r) * DD + d;
            KPs[d * FST + r] = K[g];
            Vs[r * FST + d]  = V[g];
        }
        __syncthreads();

        // Scores s[i][j] = sum_dh Qs[dh][row] * K[dh][col]
        float s[4][4];
#pragma unroll
        for (int i = 0; i < 4; i++)
#pragma unroll
            for (int j = 0; j < 4; j++) s[i][j] = 0.0f;

#pragma unroll 8
        for (int k = 0; k < 64; k++) {
            float4 a4 = *(const float4*)&Qs[k * FST + tr * 4];
            float4 b4 = *(const float4*)&KPs[k * FST + tc * 4];
            float a[4] = {a4.x, a4.y, a4.z, a4.w};
            float bb[4] = {b4.x, b4.y, b4.z, b4.w};
#pragma unroll
            for (int i = 0; i < 4; i++)
#pragma unroll
                for (int j = 0; j < 4; j++)
                    s[i][j] += a[i] * bb[j];
        }
        __syncthreads();   // all reads of KPs done; safe to overwrite with P

        // Causal mask on the diagonal tile
        if (kt == qt) {
#pragma unroll
            for (int i = 0; i < 4; i++)
#pragma unroll
                for (int j = 0; j < 4; j++)
                    if (c0 + tc * 4 + j > s0 + tr * 4 + i) s[i][j] = -1e30f;
        }

        // Row max across this tile (16 threads share each tr group)
        float mt[4];
#pragma unroll
        for (int i = 0; i < 4; i++)
            mt[i] = fmaxf(fmaxf(s[i][0], s[i][1]), fmaxf(s[i][2], s[i][3]));
#pragma unroll
        for (int off = 8; off; off >>= 1)
#pragma unroll
            for (int i = 0; i < 4; i++)
                mt[i] = fmaxf(mt[i], __shfl_xor_sync(0xffffffffu, mt[i], off));

        float p[4][4];
        float rs[4];
#pragma unroll
        for (int i = 0; i < 4; i++) {
            float mnew = fmaxf(mrun[i], mt[i]);
            float corr = __expf(mrun[i] - mnew);
            mrun[i] = mnew;
            float sum = 0.0f;
#pragma unroll
            for (int j = 0; j < 4; j++) {
                p[i][j] = __expf(s[i][j] - mnew);
                sum += p[i][j];
            }
            rs[i] = sum;
#pragma unroll
            for (int j = 0; j < 4; j++) o[i][j] *= corr;
            lrun[i] *= corr;
        }
#pragma unroll
        for (int off = 8; off; off >>= 1)
#pragma unroll
            for (int i = 0; i < 4; i++)
                rs[i] += __shfl_xor_sync(0xffffffffu, rs[i], off);
#pragma unroll
        for (int i = 0; i < 4; i++) lrun[i] += rs[i];

        // Write P transposed into KPs: KPs[c][r] = p
#pragma unroll
        for (int i = 0; i < 4; i++)
#pragma unroll
            for (int j = 0; j < 4; j++)
                KPs[(tc * 4 + j) * FST + (tr * 4 + i)] = p[i][j];
        __syncthreads();

        // O += P @ V
#pragma unroll 8
        for (int c = 0; c < 64; c++) {
            float4 pa = *(const float4*)&KPs[c * FST + tr * 4];
            float4 vb = *(const float4*)&Vs[c * FST + tc * 4];
            float a[4] = {pa.x, pa.y, pa.z, pa.w};
            float bb[4] = {vb.x, vb.y, vb.z, vb.w};
#pragma unroll
            for (int i = 0; i < 4; i++)
#pragma unroll
                for (int j = 0; j < 4; j++)
                    o[i][j] += a[i] * bb[j];
        }
        __syncthreads();   // before next tile overwrites KPs / Vs
    }

    // Normalize and write ctx in [B, S, D] layout
#pragma unroll
    for (int i = 0; i < 4; i++) {
        float inv = 1.0f / lrun[i];
        int sgl = s0 + tr * 4 + i;
#pragma unroll
        for (int j = 0; j < 4; j++) {
            O[((size_t)b * SS + sgl) * DD + h * DH + tc * 4 + j] = o[i][j] * inv;
        }
    }
}

// ---------------------------------------------------------------------------
// Launch
// ---------------------------------------------------------------------------
extern "C" void kernel_launch(void* const* d_in, const int* in_sizes, int n_in,
                              void* d_out, int out_size)
{
    const float* q  = (const float*)d_in[0];
    const float* k  = (const float*)d_in[1];
    const float* v  = (const float*)d_in[2];
    // d_in[3] = mask (causal tril; implemented analytically)
    const float* wq = (const float*)d_in[4];
    const float* bq = (const float*)d_in[5];
    const float* wk = (const float*)d_in[6];
    const float* bk = (const float*)d_in[7];
    const float* wv = (const float*)d_in[8];
    const float* bv = (const float*)d_in[9];
    const float* wo = (const float*)d_in[10];
    const float* bo = (const float*)d_in[11];
    float* out = (float*)d_out;

    float *Qh, *Kh, *Vh, *Ctx;
    cudaGetSymbolAddress((void**)&Qh,  g_Qh);
    cudaGetSymbolAddress((void**)&Kh,  g_Kh);
    cudaGetSymbolAddress((void**)&Vh,  g_Vh);
    cudaGetSymbolAddress((void**)&Ctx, g_Ctx);

    cudaFuncSetAttribute(flash_attn, cudaFuncAttributeMaxDynamicSharedMemorySize,
                         FLASH_SMEM);

    dim3 gg(DD / GBN, MM / GBM);   // (8, 128)
    gemm_nt_bias<<<gg, 256>>>(q, wq, bq, Qh);
    gemm_nt_bias<<<gg, 256>>>(k, wk, bk, Kh);
    gemm_nt_bias<<<gg, 256>>>(v, wv, bv, Vh);

    dim3 fg(SS / 64, HH, BB);      // (32, 16, 4)
    flash_attn<<<fg, 256, FLASH_SMEM>>>(Qh, Kh, Vh, Ctx);

    gemm_nt_bias<<<gg, 256>>>(Ctx, wo, bo, out);
}

// round 2
// speedup vs baseline: 1.5542x; 1.5542x over previous
#include <cuda_runtime.h>
#include <cuda_bf16.h>
#include <math.h>

// Problem constants
#define BB 4
#define SS 2048
#define DD 1024
#define HH 16
#define DH 64
#define MM (BB * SS)   // 8192

// ---------------------------------------------------------------------------
// Scratch (device globals; allocation inside kernel_launch is forbidden)
// ---------------------------------------------------------------------------
__device__ float g_Qh[(size_t)MM * DD];
__device__ float g_Kh[(size_t)MM * DD];
__device__ float g_Vh[(size_t)MM * DD];
__device__ float g_Ctx[(size_t)MM * DD];

__device__ __nv_bfloat16 g_Ahi[(size_t)MM * DD];
__device__ __nv_bfloat16 g_Alo[(size_t)MM * DD];
__device__ __nv_bfloat16 g_Whi[(size_t)DD * DD];
__device__ __nv_bfloat16 g_Wlo[(size_t)DD * DD];

// ---------------------------------------------------------------------------
// Split fp32 -> bf16 hi + bf16 lo  (x ~= hi + lo, residual ~2^-18 * |x|)
// ---------------------------------------------------------------------------
__global__ __launch_bounds__(256) void split_bf16(
    const float* __restrict__ X,
    __nv_bfloat16* __restrict__ hi, __nv_bfloat16* __restrict__ lo, int n4)
{
    int i = blockIdx.x * blockDim.x + threadIdx.x;
    if (i >= n4) return;
    float4 x = ((const float4*)X)[i];
    __nv_bfloat16 h0 = __float2bfloat16(x.x);
    __nv_bfloat16 h1 = __float2bfloat16(x.y);
    __nv_bfloat16 h2 = __float2bfloat16(x.z);
    __nv_bfloat16 h3 = __float2bfloat16(x.w);
    __nv_bfloat16 l0 = __float2bfloat16(x.x - __bfloat162float(h0));
    __nv_bfloat16 l1 = __float2bfloat16(x.y - __bfloat162float(h1));
    __nv_bfloat16 l2 = __float2bfloat16(x.z - __bfloat162float(h2));
    __nv_bfloat16 l3 = __float2bfloat16(x.w - __bfloat162float(h3));
    __nv_bfloat162* H = (__nv_bfloat162*)(hi + (size_t)i * 4);
    __nv_bfloat162* L = (__nv_bfloat162*)(lo + (size_t)i * 4);
    H[0] = __nv_bfloat162(h0, h1);
    H[1] = __nv_bfloat162(h2, h3);
    L[0] = __nv_bfloat162(l0, l1);
    L[1] = __nv_bfloat162(l2, l3);
}

// ---------------------------------------------------------------------------
// Split-bf16 tensor-core GEMM:
//   C[m,n] = sum_k A[m,k]*W[n,k] + bias[n]
// via  A_hi@W_hi + A_hi@W_lo + A_lo@W_hi  (K extended 1024 -> 3*1024)
// Tiles: BM=128, BN=128, BK=32, 256 threads, warp tile 64x32,
// mma.sync.m16n8k16.bf16, fp32 accumulate.
// smem rows padded to 40 bf16 (20 u32) -> conflict-free fragment LDS.
// ---------------------------------------------------------------------------
#define TBM 128
#define TBN 128
#define TBK 32
#define TLDA 40          // bf16 per smem row (32 + 8 pad); 20 u32
#define NKT 96           // 3 * (1024/32)

__device__ __forceinline__ void mma16816(float* c, const unsigned* a, const unsigned* b)
{
    asm volatile(
        "mma.sync.aligned.m16n8k16.row.col.f32.bf16.bf16.f32 "
        "{%0,%1,%2,%3}, {%4,%5,%6,%7}, {%8,%9}, {%0,%1,%2,%3};\n"
        : "+f"(c[0]), "+f"(c[1]), "+f"(c[2]), "+f"(c[3])
        : "r"(a[0]), "r"(a[1]), "r"(a[2]), "r"(a[3]), "r"(b[0]), "r"(b[1]));
}

__global__ __launch_bounds__(256, 2) void gemm_bf16split(
    const __nv_bfloat16* __restrict__ Ahi, const __nv_bfloat16* __restrict__ Alo,
    const __nv_bfloat16* __restrict__ Whi, const __nv_bfloat16* __restrict__ Wlo,
    const float* __restrict__ bias, float* __restrict__ C)
{
    __shared__ __align__(16) __nv_bfloat16 As[TBM * TLDA];
    __shared__ __align__(16) __nv_bfloat16 Bs[TBN * TLDA];

    const int tid  = threadIdx.x;
    const int wid  = tid >> 5;
    const int lane = tid & 31;
    const int g    = lane >> 2;      // 0..7
    const int tig  = lane & 3;       // 0..3
    const int wr   = wid >> 2;       // 0..1 : warp row (64 rows)
    const int wc   = wid & 3;        // 0..3 : warp col (32 cols)
    const int m0   = blockIdx.y * TBM;
    const int n0   = blockIdx.x * TBN;

    // global-load mapping: chunk c = tid*2+j ; row = c>>2, koff = (c&3)*8
    const int r0 = (tid * 2) >> 2;       // row for chunk j=0
    const int o0 = ((tid * 2) & 3) * 8;
    const int r1 = (tid * 2 + 1) >> 2;
    const int o1 = ((tid * 2 + 1) & 3) * 8;

    const __nv_bfloat16* Asegs[3] = {Ahi, Ahi, Alo};
    const __nv_bfloat16* Wsegs[3] = {Whi, Wlo, Whi};

    float acc[4][4][4];
#pragma unroll
    for (int mt = 0; mt < 4; mt++)
#pragma unroll
        for (int nt = 0; nt < 4; nt++)
#pragma unroll
            for (int i = 0; i < 4; i++) acc[mt][nt][i] = 0.0f;

    uint4 pa0, pa1, pb0, pb1;
    {
        const __nv_bfloat16* A = Asegs[0];
        const __nv_bfloat16* W = Wsegs[0];
        pa0 = *(const uint4*)(A + (size_t)(m0 + r0) * DD + o0);
        pa1 = *(const uint4*)(A + (size_t)(m0 + r1) * DD + o1);
        pb0 = *(const uint4*)(W + (size_t)(n0 + r0) * DD + o0);
        pb1 = *(const uint4*)(W + (size_t)(n0 + r1) * DD + o1);
    }

    for (int kt = 0; kt < NKT; kt++) {
        *(uint4*)(As + r0 * TLDA + o0) = pa0;
        *(uint4*)(As + r1 * TLDA + o1) = pa1;
        *(uint4*)(Bs + r0 * TLDA + o0) = pb0;
        *(uint4*)(Bs + r1 * TLDA + o1) = pb1;
        __syncthreads();

        if (kt + 1 < NKT) {
            int seg = (kt + 1) >> 5;
            int k0  = ((kt + 1) & 31) * TBK;
            const __nv_bfloat16* A = Asegs[seg];
            const __nv_bfloat16* W = Wsegs[seg];
            pa0 = *(const uint4*)(A + (size_t)(m0 + r0) * DD + k0 + o0);
            pa1 = *(const uint4*)(A + (size_t)(m0 + r1) * DD + k0 + o1);
            pb0 = *(const uint4*)(W + (size_t)(n0 + r0) * DD + k0 + o0);
            pb1 = *(const uint4*)(W + (size_t)(n0 + r1) * DD + k0 + o1);
        }

        const unsigned* A32 = (const unsigned*)As;
        const unsigned* B32 = (const unsigned*)Bs;
#pragma unroll
        for (int ks = 0; ks < 2; ks++) {
            unsigned af[4][4], bf[4][2];
#pragma unroll
            for (int mt = 0; mt < 4; mt++) {
                int base = (wr * 64 + mt * 16 + g) * 20 + ks * 8 + tig;
                af[mt][0] = A32[base];
                af[mt][1] = A32[base + 8 * 20];
                af[mt][2] = A32[base + 4];
                af[mt][3] = A32[base + 8 * 20 + 4];
            }
#pragma unroll
            for (int nt = 0; nt < 4; nt++) {
                int base = (wc * 32 + nt * 8 + g) * 20 + ks * 8 + tig;
                bf[nt][0] = B32[base];
                bf[nt][1] = B32[base + 4];
            }
#pragma unroll
            for (int mt = 0; mt < 4; mt++)
#pragma unroll
                for (int nt = 0; nt < 4; nt++)
                    mma16816(acc[mt][nt], af[mt], bf[nt]);
        }
        __syncthreads();
    }

    // Epilogue: bias add, float2 stores
#pragma unroll
    for (int mt = 0; mt < 4; mt++) {
        int row = m0 + wr * 64 + mt * 16 + g;
#pragma unroll
        for (int nt = 0; nt < 4; nt++) {
            int col = n0 + wc * 32 + nt * 8 + 2 * tig;
            float b0 = bias[col], b1 = bias[col + 1];
            *(float2*)&C[(size_t)row * DD + col] =
                make_float2(acc[mt][nt][0] + b0, acc[mt][nt][1] + b1);
            *(float2*)&C[(size_t)(row + 8) * DD + col] =
                make_float2(acc[mt][nt][2] + b0, acc[mt][nt][3] + b1);
        }
    }
}

// ---------------------------------------------------------------------------
// Causal flash attention, fp32 (unchanged from round 1).
// ---------------------------------------------------------------------------
#define FST 68
#define FLASH_SMEM (3 * 64 * FST * (int)sizeof(float))  // 52224 bytes

__global__ __launch_bounds__(256) void flash_attn(
    const float* __restrict__ Q, const float* __restrict__ K,
    const float* __restrict__ V, float* __restrict__ O)
{
    extern __shared__ float sm[];
    float* Qs  = sm;                 // [dh][r]
    float* KPs = sm + 64 * FST;      // [dh][c] scores phase, then P^T [c][r]
    float* Vs  = sm + 2 * 64 * FST;  // [c][dh]

    const int tid = threadIdx.x;
    const int tr  = tid >> 4;
    const int tc  = tid & 15;
    const int qt  = blockIdx.x;
    const int h   = blockIdx.y;
    const int b   = blockIdx.z;
    const int s0  = qt * 64;

    const size_t base = ((size_t)b * SS) * DD + h * DH;

#pragma unroll
    for (int i = tid; i < 64 * 64; i += 256) {
        int r = i >> 6, d = i & 63;
        Qs[d * FST + r] = Q[base + (size_t)(s0 + r) * DD + d] * 0.125f;
    }

    float o[4][4];
    float mrun[4], lrun[4];
#pragma unroll
    for (int i = 0; i < 4; i++) {
        mrun[i] = -1e30f;
        lrun[i] = 0.0f;
#pragma unroll
        for (int j = 0; j < 4; j++) o[i][j] = 0.0f;
    }
    __syncthreads();

    for (int kt = 0; kt <= qt; kt++) {
        const int c0 = kt * 64;
#pragma unroll
        for (int i = tid; i < 64 * 64; i += 256) {
            int r = i >> 6, d = i & 63;
            size_t gg = base + (size_t)(c0 + r) * DD + d;
            KPs[d * FST + r] = K[gg];
            Vs[r * FST + d]  = V[gg];
        }
        __syncthreads();

        float s[4][4];
#pragma unroll
        for (int i = 0; i < 4; i++)
#pragma unroll
            for (int j = 0; j < 4; j++) s[i][j] = 0.0f;

#pragma unroll 8
        for (int k = 0; k < 64; k++) {
            float4 a4 = *(const float4*)&Qs[k * FST + tr * 4];
            float4 b4 = *(const float4*)&KPs[k * FST + tc * 4];
            float a[4] = {a4.x, a4.y, a4.z, a4.w};
            float bb[4] = {b4.x, b4.y, b4.z, b4.w};
#pragma unroll
            for (int i = 0; i < 4; i++)
#pragma unroll
                for (int j = 0; j < 4; j++)
                    s[i][j] += a[i] * bb[j];
        }
        __syncthreads();

        if (kt == qt) {
#pragma unroll
            for (int i = 0; i < 4; i++)
#pragma unroll
                for (int j = 0; j < 4; j++)
                    if (c0 + tc * 4 + j > s0 + tr * 4 + i) s[i][j] = -1e30f;
        }

        float mt[4];
#pragma unroll
        for (int i = 0; i < 4; i++)
            mt[i] = fmaxf(fmaxf(s[i][0], s[i][1]), fmaxf(s[i][2], s[i][3]));
#pragma unroll
        for (int off = 8; off; off >>= 1)
#pragma unroll
            for (int i = 0; i < 4; i++)
                mt[i] = fmaxf(mt[i], __shfl_xor_sync(0xffffffffu, mt[i], off));

        float p[4][4];
        float rs[4];
#pragma unroll
        for (int i = 0; i < 4; i++) {
            float mnew = fmaxf(mrun[i], mt[i]);
            float corr = __expf(mrun[i] - mnew);
            mrun[i] = mnew;
            float sum = 0.0f;
#pragma unroll
            for (int j = 0; j < 4; j++) {
                p[i][j] = __expf(s[i][j] - mnew);
                sum += p[i][j];
            }
            rs[i] = sum;
#pragma unroll
            for (int j = 0; j < 4; j++) o[i][j] *= corr;
            lrun[i] *= corr;
        }
#pragma unroll
        for (int off = 8; off; off >>= 1)
#pragma unroll
            for (int i = 0; i < 4; i++)
                rs[i] += __shfl_xor_sync(0xffffffffu, rs[i], off);
#pragma unroll
        for (int i = 0; i < 4; i++) lrun[i] += rs[i];

#pragma unroll
        for (int i = 0; i < 4; i++)
#pragma unroll
            for (int j = 0; j < 4; j++)
                KPs[(tc * 4 + j) * FST + (tr * 4 + i)] = p[i][j];
        __syncthreads();

#pragma unroll 8
        for (int c = 0; c < 64; c++) {
            float4 pa = *(const float4*)&KPs[c * FST + tr * 4];
            float4 vb = *(const float4*)&Vs[c * FST + tc * 4];
            float a[4] = {pa.x, pa.y, pa.z, pa.w};
            float bb[4] = {vb.x, vb.y, vb.z, vb.w};
#pragma unroll
            for (int i = 0; i < 4; i++)
#pragma unroll
                for (int j = 0; j < 4; j++)
                    o[i][j] += a[i] * bb[j];
        }
        __syncthreads();
    }

#pragma unroll
    for (int i = 0; i < 4; i++) {
        float inv = 1.0f / lrun[i];
        int sgl = s0 + tr * 4 + i;
#pragma unroll
        for (int j = 0; j < 4; j++) {
            O[((size_t)b * SS + sgl) * DD + h * DH + tc * 4 + j] = o[i][j] * inv;
        }
    }
}

// ---------------------------------------------------------------------------
// Launch
// ---------------------------------------------------------------------------
extern "C" void kernel_launch(void* const* d_in, const int* in_sizes, int n_in,
                              void* d_out, int out_size)
{
    const float* q  = (const float*)d_in[0];
    const float* k  = (const float*)d_in[1];
    const float* v  = (const float*)d_in[2];
    // d_in[3] = mask (causal tril; implemented analytically)
    const float* wq = (const float*)d_in[4];
    const float* bq = (const float*)d_in[5];
    const float* wk = (const float*)d_in[6];
    const float* bk = (const float*)d_in[7];
    const float* wv = (const float*)d_in[8];
    const float* bv = (const float*)d_in[9];
    const float* wo = (const float*)d_in[10];
    const float* bo = (const float*)d_in[11];
    float* out = (float*)d_out;

    float *Qh, *Kh, *Vh, *Ctx;
    __nv_bfloat16 *Ahi, *Alo, *Whi, *Wlo;
    cudaGetSymbolAddress((void**)&Qh,  g_Qh);
    cudaGetSymbolAddress((void**)&Kh,  g_Kh);
    cudaGetSymbolAddress((void**)&Vh,  g_Vh);
    cudaGetSymbolAddress((void**)&Ctx, g_Ctx);
    cudaGetSymbolAddress((void**)&Ahi, g_Ahi);
    cudaGetSymbolAddress((void**)&Alo, g_Alo);
    cudaGetSymbolAddress((void**)&Whi, g_Whi);
    cudaGetSymbolAddress((void**)&Wlo, g_Wlo);

    cudaFuncSetAttribute(flash_attn, cudaFuncAttributeMaxDynamicSharedMemorySize,
                         FLASH_SMEM);

    const int nA4 = (MM * DD) / 4;      // activation elements / 4
    const int nW4 = (DD * DD) / 4;      // weight elements / 4
    dim3 sa((nA4 + 255) / 256), sw((nW4 + 255) / 256);
    dim3 gg(DD / TBN, MM / TBM);        // (8, 64)

    // Q projection
    split_bf16<<<sa, 256>>>(q,  Ahi, Alo, nA4);
    split_bf16<<<sw, 256>>>(wq, Whi, Wlo, nW4);
    gemm_bf16split<<<gg, 256>>>(Ahi, Alo, Whi, Wlo, bq, Qh);
    // K projection
    split_bf16<<<sa, 256>>>(k,  Ahi, Alo, nA4);
    split_bf16<<<sw, 256>>>(wk, Whi, Wlo, nW4);
    gemm_bf16split<<<gg, 256>>>(Ahi, Alo, Whi, Wlo, bk, Kh);
    // V projection
    split_bf16<<<sa, 256>>>(v,  Ahi, Alo, nA4);
    split_bf16<<<sw, 256>>>(wv, Whi, Wlo, nW4);
    gemm_bf16split<<<gg, 256>>>(Ahi, Alo, Whi, Wlo, bv, Vh);

    // Attention
    dim3 fg(SS / 64, HH, BB);           // (32, 16, 4)
    flash_attn<<<fg, 256, FLASH_SMEM>>>(Qh, Kh, Vh, Ctx);

    // Output projection
    split_bf16<<<sa, 256>>>(Ctx, Ahi, Alo, nA4);
    split_bf16<<<sw, 256>>>(wo,  Whi, Wlo, nW4);
    gemm_bf16split<<<gg, 256>>>(Ahi, Alo, Whi, Wlo, bo, out);
}

// round 3
// speedup vs baseline: 2.1922x; 1.4105x over previous
#include <cuda_runtime.h>
#include <cuda_bf16.h>
#include <math.h>

// Problem constants
#define BB 4
#define SS 2048
#define DD 1024
#define HH 16
#define DH 64
#define MM (BB * SS)   // 8192

// ---------------------------------------------------------------------------
// Scratch (device globals)
// ---------------------------------------------------------------------------
__device__ float g_Qh[(size_t)MM * DD];
__device__ float g_Kh[(size_t)MM * DD];
__device__ float g_Vh[(size_t)MM * DD];
__device__ float g_Ctx[(size_t)MM * DD];

__device__ __nv_bfloat16 g_Ahi[(size_t)MM * DD];
__device__ __nv_bfloat16 g_Alo[(size_t)MM * DD];
__device__ __nv_bfloat16 g_Whi[(size_t)DD * DD];
__device__ __nv_bfloat16 g_Wlo[(size_t)DD * DD];

// ---------------------------------------------------------------------------
// mma.sync m16n8k16 bf16 -> fp32
// ---------------------------------------------------------------------------
__device__ __forceinline__ void mma16816(float* c, const unsigned* a, const unsigned* b)
{
    asm volatile(
        "mma.sync.aligned.m16n8k16.row.col.f32.bf16.bf16.f32 "
        "{%0,%1,%2,%3}, {%4,%5,%6,%7}, {%8,%9}, {%0,%1,%2,%3};\n"
        : "+f"(c[0]), "+f"(c[1]), "+f"(c[2]), "+f"(c[3])
        : "r"(a[0]), "r"(a[1]), "r"(a[2]), "r"(a[3]), "r"(b[0]), "r"(b[1]));
}

__device__ __forceinline__ void split2(float x, float y, unsigned& hi, unsigned& lo)
{
    __nv_bfloat16 hx = __float2bfloat16(x);
    __nv_bfloat16 hy = __float2bfloat16(y);
    float rx = x - __bfloat162float(hx);
    float ry = y - __bfloat162float(hy);
    __nv_bfloat162 H(hx, hy);
    __nv_bfloat162 L(__float2bfloat16(rx), __float2bfloat16(ry));
    hi = *(unsigned*)&H;
    lo = *(unsigned*)&L;
}

// ---------------------------------------------------------------------------
// Split fp32 -> bf16 hi + lo (standalone, for GEMM inputs)
// ---------------------------------------------------------------------------
__global__ __launch_bounds__(256) void split_bf16(
    const float* __restrict__ X,
    __nv_bfloat16* __restrict__ hi, __nv_bfloat16* __restrict__ lo, int n4)
{
    int i = blockIdx.x * blockDim.x + threadIdx.x;
    if (i >= n4) return;
    float4 x = ((const float4*)X)[i];
    unsigned h0, l0, h1, l1;
    split2(x.x, x.y, h0, l0);
    split2(x.z, x.w, h1, l1);
    unsigned* H = (unsigned*)(hi + (size_t)i * 4);
    unsigned* L = (unsigned*)(lo + (size_t)i * 4);
    H[0] = h0; H[1] = h1;
    L[0] = l0; L[1] = l1;
}

// ---------------------------------------------------------------------------
// Split-bf16 tensor-core GEMM (unchanged from round 1)
// ---------------------------------------------------------------------------
#define TBM 128
#define TBN 128
#define TBK 32
#define TLDA 40
#define NKT 96

__global__ __launch_bounds__(256, 2) void gemm_bf16split(
    const __nv_bfloat16* __restrict__ Ahi, const __nv_bfloat16* __restrict__ Alo,
    const __nv_bfloat16* __restrict__ Whi, const __nv_bfloat16* __restrict__ Wlo,
    const float* __restrict__ bias, float* __restrict__ C)
{
    __shared__ __align__(16) __nv_bfloat16 As[TBM * TLDA];
    __shared__ __align__(16) __nv_bfloat16 Bs[TBN * TLDA];

    const int tid  = threadIdx.x;
    const int wid  = tid >> 5;
    const int lane = tid & 31;
    const int g    = lane >> 2;
    const int tig  = lane & 3;
    const int wr   = wid >> 2;
    const int wc   = wid & 3;
    const int m0   = blockIdx.y * TBM;
    const int n0   = blockIdx.x * TBN;

    const int r0 = (tid * 2) >> 2;
    const int o0 = ((tid * 2) & 3) * 8;
    const int r1 = (tid * 2 + 1) >> 2;
    const int o1 = ((tid * 2 + 1) & 3) * 8;

    const __nv_bfloat16* Asegs[3] = {Ahi, Ahi, Alo};
    const __nv_bfloat16* Wsegs[3] = {Whi, Wlo, Whi};

    float acc[4][4][4];
#pragma unroll
    for (int mt = 0; mt < 4; mt++)
#pragma unroll
        for (int nt = 0; nt < 4; nt++)
#pragma unroll
            for (int i = 0; i < 4; i++) acc[mt][nt][i] = 0.0f;

    uint4 pa0, pa1, pb0, pb1;
    {
        const __nv_bfloat16* A = Asegs[0];
        const __nv_bfloat16* W = Wsegs[0];
        pa0 = *(const uint4*)(A + (size_t)(m0 + r0) * DD + o0);
        pa1 = *(const uint4*)(A + (size_t)(m0 + r1) * DD + o1);
        pb0 = *(const uint4*)(W + (size_t)(n0 + r0) * DD + o0);
        pb1 = *(const uint4*)(W + (size_t)(n0 + r1) * DD + o1);
    }

    for (int kt = 0; kt < NKT; kt++) {
        *(uint4*)(As + r0 * TLDA + o0) = pa0;
        *(uint4*)(As + r1 * TLDA + o1) = pa1;
        *(uint4*)(Bs + r0 * TLDA + o0) = pb0;
        *(uint4*)(Bs + r1 * TLDA + o1) = pb1;
        __syncthreads();

        if (kt + 1 < NKT) {
            int seg = (kt + 1) >> 5;
            int k0  = ((kt + 1) & 31) * TBK;
            const __nv_bfloat16* A = Asegs[seg];
            const __nv_bfloat16* W = Wsegs[seg];
            pa0 = *(const uint4*)(A + (size_t)(m0 + r0) * DD + k0 + o0);
            pa1 = *(const uint4*)(A + (size_t)(m0 + r1) * DD + k0 + o1);
            pb0 = *(const uint4*)(W + (size_t)(n0 + r0) * DD + k0 + o0);
            pb1 = *(const uint4*)(W + (size_t)(n0 + r1) * DD + k0 + o1);
        }

        const unsigned* A32 = (const unsigned*)As;
        const unsigned* B32 = (const unsigned*)Bs;
#pragma unroll
        for (int ks = 0; ks < 2; ks++) {
            unsigned af[4][4], bf[4][2];
#pragma unroll
            for (int mt = 0; mt < 4; mt++) {
                int base = (wr * 64 + mt * 16 + g) * 20 + ks * 8 + tig;
                af[mt][0] = A32[base];
                af[mt][1] = A32[base + 8 * 20];
                af[mt][2] = A32[base + 4];
                af[mt][3] = A32[base + 8 * 20 + 4];
            }
#pragma unroll
            for (int nt = 0; nt < 4; nt++) {
                int base = (wc * 32 + nt * 8 + g) * 20 + ks * 8 + tig;
                bf[nt][0] = B32[base];
                bf[nt][1] = B32[base + 4];
            }
#pragma unroll
            for (int mt = 0; mt < 4; mt++)
#pragma unroll
                for (int nt = 0; nt < 4; nt++)
                    mma16816(acc[mt][nt], af[mt], bf[nt]);
        }
        __syncthreads();
    }

#pragma unroll
    for (int mt = 0; mt < 4; mt++) {
        int row = m0 + wr * 64 + mt * 16 + g;
#pragma unroll
        for (int nt = 0; nt < 4; nt++) {
            int col = n0 + wc * 32 + nt * 8 + 2 * tig;
            float b0 = bias[col], b1 = bias[col + 1];
            *(float2*)&C[(size_t)row * DD + col] =
                make_float2(acc[mt][nt][0] + b0, acc[mt][nt][1] + b1);
            *(float2*)&C[(size_t)(row + 8) * DD + col] =
                make_float2(acc[mt][nt][2] + b0, acc[mt][nt][3] + b1);
        }
    }
}

// ---------------------------------------------------------------------------
// Tensor-core causal flash attention with split-bf16 compensation.
// Grid: (S/128, H, B). Block: 256 threads (8 warps).
// Warp w owns q-rows [w*16, w*16+16). Key tiles of 64.
// smem layout (bytes):
//   Qhi [128][72]bf16 : 0      (18432)
//   Qlo [128][72]     : 18432  (18432)
//   Khi [64][72]      : 36864  (9216)
//   Klo [64][72]      : 46080  (9216)
//   VhiT[64dh][74]    : 55296  (9472)
//   VloT[64dh][74]    : 64768  (9472)   total 74240
// ---------------------------------------------------------------------------
#define FA_SMEM 74240
#define QSW 36   // u32 stride of Q/K smem rows
#define VSW 37   // u32 stride of V^T smem rows

__global__ __launch_bounds__(256) void flash_attn_tc(
    const float* __restrict__ Q, const float* __restrict__ K,
    const float* __restrict__ V, float* __restrict__ O)
{
    extern __shared__ __align__(16) char smraw[];
    unsigned* QHI = (unsigned*)(smraw);
    unsigned* QLO = (unsigned*)(smraw + 18432);
    unsigned* KHI = (unsigned*)(smraw + 36864);
    unsigned* KLO = (unsigned*)(smraw + 46080);
    __nv_bfloat16* VHIb = (__nv_bfloat16*)(smraw + 55296);
    __nv_bfloat16* VLOb = (__nv_bfloat16*)(smraw + 64768);
    const unsigned* VHI = (const unsigned*)VHIb;
    const unsigned* VLO = (const unsigned*)VLOb;

    const int tid  = threadIdx.x;
    const int w    = tid >> 5;
    const int lane = tid & 31;
    const int g    = lane >> 2;
    const int tig  = lane & 3;
    const int qt   = blockIdx.x;
    const int h    = blockIdx.y;
    const int b    = blockIdx.z;
    const int s0   = qt * 128;

    const size_t base = ((size_t)b * SS) * DD + (size_t)h * DH;

    // ---- Q fill (scaled by 1/8, split to hi/lo) ----
#pragma unroll
    for (int i = tid; i < 128 * 16; i += 256) {
        int row = i >> 4, c4 = i & 15;
        float4 x = *(const float4*)(Q + base + (size_t)(s0 + row) * DD + c4 * 4);
        x.x *= 0.125f; x.y *= 0.125f; x.z *= 0.125f; x.w *= 0.125f;
        unsigned h0, l0, h1, l1;
        split2(x.x, x.y, h0, l0);
        split2(x.z, x.w, h1, l1);
        int wbase_i = row * QSW + c4 * 2;
        QHI[wbase_i] = h0; QHI[wbase_i + 1] = h1;
        QLO[wbase_i] = l0; QLO[wbase_i + 1] = l1;
    }

    float p[8][4];       // scores, then probabilities
    float o[8][4];       // output accumulators
    float mrun[2], lrun[2];
    mrun[0] = mrun[1] = -1e30f;
    lrun[0] = lrun[1] = 0.0f;
#pragma unroll
    for (int j = 0; j < 8; j++)
#pragma unroll
        for (int e = 0; e < 4; e++) o[j][e] = 0.0f;

    const int wrow = s0 + w * 16;      // warp's first global q-row
    const int nkt  = 2 * (qt + 1);

    for (int kt = 0; kt < nkt; kt++) {
        const int c0 = kt * 64;
        __syncthreads();   // previous tile's compute done (and Q fill on kt==0)

        // ---- K fill: natural [key][dh] ----
#pragma unroll
        for (int i = tid; i < 64 * 16; i += 256) {
            int key = i >> 4, c4 = i & 15;
            float4 x = *(const float4*)(K + base + (size_t)(c0 + key) * DD + c4 * 4);
            unsigned h0, l0, h1, l1;
            split2(x.x, x.y, h0, l0);
            split2(x.z, x.w, h1, l1);
            int wi = key * QSW + c4 * 2;
            KHI[wi] = h0; KHI[wi + 1] = h1;
            KLO[wi] = l0; KLO[wi + 1] = l1;
        }
        // ---- V fill: transposed [dh][key], stride 74 bf16 ----
#pragma unroll
        for (int i = tid; i < 64 * 64; i += 256) {
            int key = i >> 6, dh = i & 63;
            float x = V[base + (size_t)(c0 + key) * DD + dh];
            __nv_bfloat16 hx = __float2bfloat16(x);
            float rx = x - __bfloat162float(hx);
            VHIb[dh * 74 + key] = hx;
            VLOb[dh * 74 + key] = __float2bfloat16(rx);
        }
        __syncthreads();

        if (c0 > wrow + 15) continue;   // fully-masked tile for this warp

        // ---- S = Q K^T (3-term split) ----
#pragma unroll
        for (int j = 0; j < 8; j++)
#pragma unroll
            for (int e = 0; e < 4; e++) p[j][e] = 0.0f;

#pragma unroll
        for (int kc = 0; kc < 4; kc++) {
            int abase = (w * 16 + g) * QSW + kc * 8 + tig;
            unsigned ah[4], al[4];
            ah[0] = QHI[abase];           ah[1] = QHI[abase + 8 * QSW];
            ah[2] = QHI[abase + 4];       ah[3] = QHI[abase + 8 * QSW + 4];
            al[0] = QLO[abase];           al[1] = QLO[abase + 8 * QSW];
            al[2] = QLO[abase + 4];       al[3] = QLO[abase + 8 * QSW + 4];
#pragma unroll
            for (int j = 0; j < 8; j++) {
                int bbase = (j * 8 + g) * QSW + kc * 8 + tig;
                unsigned bh[2] = {KHI[bbase], KHI[bbase + 4]};
                unsigned bl[2] = {KLO[bbase], KLO[bbase + 4]};
                mma16816(p[j], ah, bh);
                mma16816(p[j], ah, bl);
                mma16816(p[j], al, bh);
            }
        }

        // ---- causal mask (only on partially-visible tiles) ----
        if (c0 + 63 > wrow) {
            int r0 = wrow + g, r1 = wrow + g + 8;
#pragma unroll
            for (int j = 0; j < 8; j++) {
                int cA = c0 + j * 8 + 2 * tig;
                if (cA     > r0) p[j][0] = -1e30f;
                if (cA + 1 > r0) p[j][1] = -1e30f;
                if (cA     > r1) p[j][2] = -1e30f;
                if (cA + 1 > r1) p[j][3] = -1e30f;
            }
        }

        // ---- online softmax ----
        float mt0 = -1e30f, mt1 = -1e30f;
#pragma unroll
        for (int j = 0; j < 8; j++) {
            mt0 = fmaxf(mt0, fmaxf(p[j][0], p[j][1]));
            mt1 = fmaxf(mt1, fmaxf(p[j][2], p[j][3]));
        }
        mt0 = fmaxf(mt0, __shfl_xor_sync(0xffffffffu, mt0, 1));
        mt0 = fmaxf(mt0, __shfl_xor_sync(0xffffffffu, mt0, 2));
        mt1 = fmaxf(mt1, __shfl_xor_sync(0xffffffffu, mt1, 1));
        mt1 = fmaxf(mt1, __shfl_xor_sync(0xffffffffu, mt1, 2));

        float mnew0 = fmaxf(mrun[0], mt0);
        float mnew1 = fmaxf(mrun[1], mt1);
        float corr0 = __expf(mrun[0] - mnew0);
        float corr1 = __expf(mrun[1] - mnew1);
        mrun[0] = mnew0; mrun[1] = mnew1;

        float rs0 = 0.0f, rs1 = 0.0f;
#pragma unroll
        for (int j = 0; j < 8; j++) {
            p[j][0] = __expf(p[j][0] - mnew0);
            p[j][1] = __expf(p[j][1] - mnew0);
            p[j][2] = __expf(p[j][2] - mnew1);
            p[j][3] = __expf(p[j][3] - mnew1);
            rs0 += p[j][0] + p[j][1];
            rs1 += p[j][2] + p[j][3];
            o[j][0] *= corr0; o[j][1] *= corr0;
            o[j][2] *= corr1; o[j][3] *= corr1;
        }
        rs0 += __shfl_xor_sync(0xffffffffu, rs0, 1);
        rs0 += __shfl_xor_sync(0xffffffffu, rs0, 2);
        rs1 += __shfl_xor_sync(0xffffffffu, rs1, 1);
        rs1 += __shfl_xor_sync(0xffffffffu, rs1, 2);
        lrun[0] = lrun[0] * corr0 + rs0;
        lrun[1] = lrun[1] * corr1 + rs1;

        // ---- O += P V (P packed in registers; 3-term split) ----
#pragma unroll
        for (int kc = 0; kc < 4; kc++) {
            unsigned pah[4], pal[4];
            split2(p[2 * kc][0],     p[2 * kc][1],     pah[0], pal[0]);
            split2(p[2 * kc][2],     p[2 * kc][3],     pah[1], pal[1]);
            split2(p[2 * kc + 1][0], p[2 * kc + 1][1], pah[2], pal[2]);
            split2(p[2 * kc + 1][2], p[2 * kc + 1][3], pah[3], pal[3]);
#pragma unroll
            for (int j = 0; j < 8; j++) {
                int bbase = (j * 8 + g) * VSW + kc * 8 + tig;
                unsigned bh[2] = {VHI[bbase], VHI[bbase + 4]};
                unsigned bl[2] = {VLO[bbase], VLO[bbase + 4]};
                mma16816(o[j], pah, bh);
                mma16816(o[j], pah, bl);
                mma16816(o[j], pal, bh);
            }
        }
    }

    // ---- normalize & write ctx [B,S,D] ----
    float inv0 = 1.0f / lrun[0];
    float inv1 = 1.0f / lrun[1];
#pragma unroll
    for (int j = 0; j < 8; j++) {
        int dh = j * 8 + 2 * tig;
        size_t r0 = ((size_t)b * SS + wrow + g) * DD + h * DH + dh;
        size_t r1 = ((size_t)b * SS + wrow + g + 8) * DD + h * DH + dh;
        *(float2*)&O[r0] = make_float2(o[j][0] * inv0, o[j][1] * inv0);
        *(float2*)&O[r1] = make_float2(o[j][2] * inv1, o[j][3] * inv1);
    }
}

// ---------------------------------------------------------------------------
// Launch
// ---------------------------------------------------------------------------
extern "C" void kernel_launch(void* const* d_in, const int* in_sizes, int n_in,
                              void* d_out, int out_size)
{
    const float* q  = (const float*)d_in[0];
    const float* k  = (const float*)d_in[1];
    const float* v  = (const float*)d_in[2];
    // d_in[3] = mask (causal tril; implemented analytically)
    const float* wq = (const float*)d_in[4];
    const float* bq = (const float*)d_in[5];
    const float* wk = (const float*)d_in[6];
    const float* bk = (const float*)d_in[7];
    const float* wv = (const float*)d_in[8];
    const float* bv = (const float*)d_in[9];
    const float* wo = (const float*)d_in[10];
    const float* bo = (const float*)d_in[11];
    float* out = (float*)d_out;

    float *Qh, *Kh, *Vh, *Ctx;
    __nv_bfloat16 *Ahi, *Alo, *Whi, *Wlo;
    cudaGetSymbolAddress((void**)&Qh,  g_Qh);
    cudaGetSymbolAddress((void**)&Kh,  g_Kh);
    cudaGetSymbolAddress((void**)&Vh,  g_Vh);
    cudaGetSymbolAddress((void**)&Ctx, g_Ctx);
    cudaGetSymbolAddress((void**)&Ahi, g_Ahi);
    cudaGetSymbolAddress((void**)&Alo, g_Alo);
    cudaGetSymbolAddress((void**)&Whi, g_Whi);
    cudaGetSymbolAddress((void**)&Wlo, g_Wlo);

    cudaFuncSetAttribute(flash_attn_tc, cudaFuncAttributeMaxDynamicSharedMemorySize,
                         FA_SMEM);

    const int nA4 = (MM * DD) / 4;
    const int nW4 = (DD * DD) / 4;
    dim3 sa((nA4 + 255) / 256), sw((nW4 + 255) / 256);
    dim3 gg(DD / TBN, MM / TBM);        // (8, 64)

    split_bf16<<<sa, 256>>>(q,  Ahi, Alo, nA4);
    split_bf16<<<sw, 256>>>(wq, Whi, Wlo, nW4);
    gemm_bf16split<<<gg, 256>>>(Ahi, Alo, Whi, Wlo, bq, Qh);

    split_bf16<<<sa, 256>>>(k,  Ahi, Alo, nA4);
    split_bf16<<<sw, 256>>>(wk, Whi, Wlo, nW4);
    gemm_bf16split<<<gg, 256>>>(Ahi, Alo, Whi, Wlo, bk, Kh);

    split_bf16<<<sa, 256>>>(v,  Ahi, Alo, nA4);
    split_bf16<<<sw, 256>>>(wv, Whi, Wlo, nW4);
    gemm_bf16split<<<gg, 256>>>(Ahi, Alo, Whi, Wlo, bv, Vh);

    dim3 fg(SS / 128, HH, BB);          // (16, 16, 4)
    flash_attn_tc<<<fg, 256, FA_SMEM>>>(Qh, Kh, Vh, Ctx);

    split_bf16<<<sa, 256>>>(Ctx, Ahi, Alo, nA4);
    split_bf16<<<sw, 256>>>(wo,  Whi, Wlo, nW4);
    gemm_bf16split<<<gg, 256>>>(Ahi, Alo, Whi, Wlo, bo, out);
}

// round 6
// speedup vs baseline: 2.2544x; 1.0284x over previous
#include <cuda_runtime.h>
#include <cuda_fp16.h>
#include <math.h>

// Problem constants
#define BB 4
#define SS 2048
#define DD 1024
#define HH 16
#define DH 64
#define MM (BB * SS)   // 8192

#define MASKV  (-1e4f)   // finite mask sentinel (log2-domain scores are |s| <~ 30)
#define YCLAMP (-30.0f)  // 2^-30 underflows to 0 in f16 exp output

// ---------------------------------------------------------------------------
// Scratch (device globals)
// ---------------------------------------------------------------------------
__device__ float g_Ctx[(size_t)MM * DD];

__device__ __half g_Ahi[(size_t)MM * DD];
__device__ __half g_Alo[(size_t)MM * DD];
__device__ __half g_Whi[(size_t)DD * DD];
__device__ __half g_Wlo[(size_t)DD * DD];

__device__ __half g_Qhi[(size_t)MM * DD];
__device__ __half g_Qlo[(size_t)MM * DD];
__device__ __half g_Khi[(size_t)MM * DD];
__device__ __half g_Klo[(size_t)MM * DD];
__device__ __half g_Vhi[(size_t)MM * DD];
__device__ __half g_Vlo[(size_t)MM * DD];

// ---------------------------------------------------------------------------
// mma.sync m16n8k16 f16 -> fp32
// ---------------------------------------------------------------------------
__device__ __forceinline__ void mma16816h(float* c, const unsigned* a, const unsigned* b)
{
    asm volatile(
        "mma.sync.aligned.m16n8k16.row.col.f32.f16.f16.f32 "
        "{%0,%1,%2,%3}, {%4,%5,%6,%7}, {%8,%9}, {%0,%1,%2,%3};\n"
        : "+f"(c[0]), "+f"(c[1]), "+f"(c[2]), "+f"(c[3])
        : "r"(a[0]), "r"(a[1]), "r"(a[2]), "r"(a[3]), "r"(b[0]), "r"(b[1]));
}

__device__ __forceinline__ void split2h(float x, float y, unsigned& hi, unsigned& lo)
{
    __half hx = __float2half(x);
    __half hy = __float2half(y);
    float rx = x - __half2float(hx);
    float ry = y - __half2float(hy);
    __half2 H(hx, hy);
    __half2 L(__float2half(rx), __float2half(ry));
    hi = *(unsigned*)&H;
    lo = *(unsigned*)&L;
}

// ---------------------------------------------------------------------------
// Split fp32 -> f16 hi + lo (GEMM inputs)
// ---------------------------------------------------------------------------
__global__ __launch_bounds__(256) void split_f16(
    const float* __restrict__ X,
    __half* __restrict__ hi, __half* __restrict__ lo, int n4)
{
    int i = blockIdx.x * blockDim.x + threadIdx.x;
    if (i >= n4) return;
    float4 x = ((const float4*)X)[i];
    unsigned h0, l0, h1, l1;
    split2h(x.x, x.y, h0, l0);
    split2h(x.z, x.w, h1, l1);
    unsigned* H = (unsigned*)(hi + (size_t)i * 4);
    unsigned* L = (unsigned*)(lo + (size_t)i * 4);
    H[0] = h0; H[1] = h1;
    L[0] = l0; L[1] = l1;
}

// ---------------------------------------------------------------------------
// Split-f16 tensor-core GEMM:  C[m,n] = (sum_k A[m,k]*W[n,k] + bias[n])*scale
// 3-term compensation: Ahi@Whi + Ahi@Wlo + Alo@Whi.
// SPLITOUT=true: write f16 hi/lo pair arrays. false: write fp32 C.
// ---------------------------------------------------------------------------
#define TBM 128
#define TBN 128
#define TBK 32
#define TLDA 40          // halves per smem row (32 + 8 pad); 20 u32
#define NKT 96           // 3 * (1024/32)

template<bool SPLITOUT>
__global__ __launch_bounds__(256, 2) void gemm_f16split(
    const __half* __restrict__ Ahi, const __half* __restrict__ Alo,
    const __half* __restrict__ Whi, const __half* __restrict__ Wlo,
    const float* __restrict__ bias, float scale,
    float* __restrict__ C, __half* __restrict__ Chi, __half* __restrict__ Clo)
{
    __shared__ __align__(16) __half As[TBM * TLDA];
    __shared__ __align__(16) __half Bs[TBN * TLDA];

    const int tid  = threadIdx.x;
    const int wid  = tid >> 5;
    const int lane = tid & 31;
    const int g    = lane >> 2;
    const int tig  = lane & 3;
    const int wr   = wid >> 2;
    const int wc   = wid & 3;
    const int m0   = blockIdx.y * TBM;
    const int n0   = blockIdx.x * TBN;

    const int r0 = (tid * 2) >> 2;
    const int o0 = ((tid * 2) & 3) * 8;
    const int r1 = (tid * 2 + 1) >> 2;
    const int o1 = ((tid * 2 + 1) & 3) * 8;

    const __half* Asegs[3] = {Ahi, Ahi, Alo};
    const __half* Wsegs[3] = {Whi, Wlo, Whi};

    float acc[4][4][4];
#pragma unroll
    for (int mt = 0; mt < 4; mt++)
#pragma unroll
        for (int nt = 0; nt < 4; nt++)
#pragma unroll
            for (int i = 0; i < 4; i++) acc[mt][nt][i] = 0.0f;

    uint4 pa0, pa1, pb0, pb1;
    {
        const __half* A = Asegs[0];
        const __half* W = Wsegs[0];
        pa0 = *(const uint4*)(A + (size_t)(m0 + r0) * DD + o0);
        pa1 = *(const uint4*)(A + (size_t)(m0 + r1) * DD + o1);
        pb0 = *(const uint4*)(W + (size_t)(n0 + r0) * DD + o0);
        pb1 = *(const uint4*)(W + (size_t)(n0 + r1) * DD + o1);
    }

    for (int kt = 0; kt < NKT; kt++) {
        *(uint4*)(As + r0 * TLDA + o0) = pa0;
        *(uint4*)(As + r1 * TLDA + o1) = pa1;
        *(uint4*)(Bs + r0 * TLDA + o0) = pb0;
        *(uint4*)(Bs + r1 * TLDA + o1) = pb1;
        __syncthreads();

        if (kt + 1 < NKT) {
            int seg = (kt + 1) >> 5;
            int k0  = ((kt + 1) & 31) * TBK;
            const __half* A = Asegs[seg];
            const __half* W = Wsegs[seg];
            pa0 = *(const uint4*)(A + (size_t)(m0 + r0) * DD + k0 + o0);
            pa1 = *(const uint4*)(A + (size_t)(m0 + r1) * DD + k0 + o1);
            pb0 = *(const uint4*)(W + (size_t)(n0 + r0) * DD + k0 + o0);
            pb1 = *(const uint4*)(W + (size_t)(n0 + r1) * DD + k0 + o1);
        }

        const unsigned* A32 = (const unsigned*)As;
        const unsigned* B32 = (const unsigned*)Bs;
#pragma unroll
        for (int ks = 0; ks < 2; ks++) {
            unsigned af[4][4], bf[4][2];
#pragma unroll
            for (int mt = 0; mt < 4; mt++) {
                int base = (wr * 64 + mt * 16 + g) * 20 + ks * 8 + tig;
                af[mt][0] = A32[base];
                af[mt][1] = A32[base + 8 * 20];
                af[mt][2] = A32[base + 4];
                af[mt][3] = A32[base + 8 * 20 + 4];
            }
#pragma unroll
            for (int nt = 0; nt < 4; nt++) {
                int base = (wc * 32 + nt * 8 + g) * 20 + ks * 8 + tig;
                bf[nt][0] = B32[base];
                bf[nt][1] = B32[base + 4];
            }
#pragma unroll
            for (int mt = 0; mt < 4; mt++)
#pragma unroll
                for (int nt = 0; nt < 4; nt++)
                    mma16816h(acc[mt][nt], af[mt], bf[nt]);
        }
        __syncthreads();
    }

#pragma unroll
    for (int mt = 0; mt < 4; mt++) {
        int row = m0 + wr * 64 + mt * 16 + g;
#pragma unroll
        for (int nt = 0; nt < 4; nt++) {
            int col = n0 + wc * 32 + nt * 8 + 2 * tig;
            float b0 = bias[col], b1 = bias[col + 1];
            float v0 = (acc[mt][nt][0] + b0) * scale;
            float v1 = (acc[mt][nt][1] + b1) * scale;
            float v2 = (acc[mt][nt][2] + b0) * scale;
            float v3 = (acc[mt][nt][3] + b1) * scale;
            if (SPLITOUT) {
                unsigned h01, l01, h23, l23;
                split2h(v0, v1, h01, l01);
                split2h(v2, v3, h23, l23);
                *(unsigned*)(Chi + (size_t)row * DD + col) = h01;
                *(unsigned*)(Clo + (size_t)row * DD + col) = l01;
                *(unsigned*)(Chi + (size_t)(row + 8) * DD + col) = h23;
                *(unsigned*)(Clo + (size_t)(row + 8) * DD + col) = l23;
            } else {
                *(float2*)&C[(size_t)row * DD + col] = make_float2(v0, v1);
                *(float2*)&C[(size_t)(row + 8) * DD + col] = make_float2(v2, v3);
            }
        }
    }
}

// ---------------------------------------------------------------------------
// Tensor-core causal flash attention (f16 split inputs, log2-domain softmax,
// f16x2 MUFU exp with clamp, P kept in registers as f16, l via ones MMA).
// Grid: (S/128, H, B). Block: 256 threads (8 warps).
// smem: Qhi[128][72]h, Qlo, Khi[64][72], Klo, VhiT[64][74], VloT  = 74240 B
// ---------------------------------------------------------------------------
#define FA_SMEM 74240
#define QSW 36   // u32 stride of Q/K smem rows (72 halves + pad)
#define VSW 37   // u32 stride of V^T smem rows (74 halves)

__global__ __launch_bounds__(256) void flash_attn_tc(
    const __half* __restrict__ Qhi_, const __half* __restrict__ Qlo_,
    const __half* __restrict__ Khi_, const __half* __restrict__ Klo_,
    const __half* __restrict__ Vhi_, const __half* __restrict__ Vlo_,
    float* __restrict__ O)
{
    extern __shared__ __align__(16) char smraw[];
    unsigned* QHI = (unsigned*)(smraw);
    unsigned* QLO = (unsigned*)(smraw + 18432);
    unsigned* KHI = (unsigned*)(smraw + 36864);
    unsigned* KLO = (unsigned*)(smraw + 46080);
    __half*   VHIb = (__half*)(smraw + 55296);
    __half*   VLOb = (__half*)(smraw + 64768);
    const unsigned* VHI = (const unsigned*)VHIb;
    const unsigned* VLO = (const unsigned*)VLOb;

    const int tid  = threadIdx.x;
    const int w    = tid >> 5;
    const int lane = tid & 31;
    const int g    = lane >> 2;
    const int tig  = lane & 3;
    const int qt   = blockIdx.x;
    const int h    = blockIdx.y;
    const int b    = blockIdx.z;
    const int s0   = qt * 128;

    const size_t base = ((size_t)b * SS) * DD + (size_t)h * DH;

    // ---- Q fill: FULL rows — 128 rows x 8 uint4 chunks (64 halves/row) ----
#pragma unroll
    for (int i = tid; i < 128 * 8; i += 256) {
        int row = i >> 3, c4 = i & 7;
        size_t gidx = base + (size_t)(s0 + row) * DD + c4 * 8;
        *(uint4*)(QHI + row * QSW + c4 * 4) = *(const uint4*)(Qhi_ + gidx);
        *(uint4*)(QLO + row * QSW + c4 * 4) = *(const uint4*)(Qlo_ + gidx);
    }

    float o[8][4];
    float mrun0 = MASKV, mrun1 = MASKV;
    float lrun0 = 0.0f,  lrun1 = 0.0f;
#pragma unroll
    for (int j = 0; j < 8; j++)
#pragma unroll
        for (int e = 0; e < 4; e++) o[j][e] = 0.0f;

    const int wrow = s0 + w * 16;
    const int nkt  = 2 * (qt + 1);

    for (int kt = 0; kt < nkt; kt++) {
        const int c0 = kt * 64;
        __syncthreads();

        // ---- K fill: FULL rows — 64 rows x 8 uint4 chunks ----
#pragma unroll
        for (int i = tid; i < 64 * 8; i += 256) {
            int row = i >> 3, c4 = i & 7;
            size_t gidx = base + (size_t)(c0 + row) * DD + c4 * 8;
            *(uint4*)(KHI + row * QSW + c4 * 4) = *(const uint4*)(Khi_ + gidx);
            *(uint4*)(KLO + row * QSW + c4 * 4) = *(const uint4*)(Klo_ + gidx);
        }
        // ---- V fill: transpose to [dh][key], stride 74 halves ----
#pragma unroll
        for (int i = tid; i < 64 * 32; i += 256) {
            int key = i >> 5, d2 = i & 31;
            size_t gidx = base + (size_t)(c0 + key) * DD + d2 * 2;
            __half2 hv = *(const __half2*)(Vhi_ + gidx);
            __half2 lv = *(const __half2*)(Vlo_ + gidx);
            VHIb[(2 * d2) * 74 + key]     = __low2half(hv);
            VHIb[(2 * d2 + 1) * 74 + key] = __high2half(hv);
            VLOb[(2 * d2) * 74 + key]     = __low2half(lv);
            VLOb[(2 * d2 + 1) * 74 + key] = __high2half(lv);
        }
        __syncthreads();

        if (c0 > wrow + 15) continue;

        // ---- S = Q K^T (3-term f16 split; already in log2 domain) ----
        float p[8][4];
#pragma unroll
        for (int j = 0; j < 8; j++)
#pragma unroll
            for (int e = 0; e < 4; e++) p[j][e] = 0.0f;

#pragma unroll
        for (int kc = 0; kc < 4; kc++) {
            int abase = (w * 16 + g) * QSW + kc * 8 + tig;
            unsigned ah[4], al[4];
            ah[0] = QHI[abase];           ah[1] = QHI[abase + 8 * QSW];
            ah[2] = QHI[abase + 4];       ah[3] = QHI[abase + 8 * QSW + 4];
            al[0] = QLO[abase];           al[1] = QLO[abase + 8 * QSW];
            al[2] = QLO[abase + 4];       al[3] = QLO[abase + 8 * QSW + 4];
#pragma unroll
            for (int j = 0; j < 8; j++) {
                int bbase = (j * 8 + g) * QSW + kc * 8 + tig;
                unsigned bh[2] = {KHI[bbase], KHI[bbase + 4]};
                unsigned bl[2] = {KLO[bbase], KLO[bbase + 4]};
                mma16816h(p[j], ah, bh);
                mma16816h(p[j], ah, bl);
                mma16816h(p[j], al, bh);
            }
        }

        // ---- causal mask (finite sentinel) ----
        if (c0 + 63 > wrow) {
            int r0 = wrow + g, r1 = wrow + g + 8;
#pragma unroll
            for (int j = 0; j < 8; j++) {
                int cA = c0 + j * 8 + 2 * tig;
                if (cA     > r0) p[j][0] = MASKV;
                if (cA + 1 > r0) p[j][1] = MASKV;
                if (cA     > r1) p[j][2] = MASKV;
                if (cA + 1 > r1) p[j][3] = MASKV;
            }
        }

        // ---- row max ----
        float mt0 = MASKV, mt1 = MASKV;
#pragma unroll
        for (int j = 0; j < 8; j++) {
            mt0 = fmaxf(mt0, fmaxf(p[j][0], p[j][1]));
            mt1 = fmaxf(mt1, fmaxf(p[j][2], p[j][3]));
        }
        mt0 = fmaxf(mt0, __shfl_xor_sync(0xffffffffu, mt0, 1));
        mt0 = fmaxf(mt0, __shfl_xor_sync(0xffffffffu, mt0, 2));
        mt1 = fmaxf(mt1, __shfl_xor_sync(0xffffffffu, mt1, 1));
        mt1 = fmaxf(mt1, __shfl_xor_sync(0xffffffffu, mt1, 2));

        float mnew0 = fmaxf(mrun0, mt0);
        float mnew1 = fmaxf(mrun1, mt1);
        float corr0, corr1;
        {
            float d0 = fmaxf(mrun0 - mnew0, -126.0f);
            float d1 = fmaxf(mrun1 - mnew1, -126.0f);
            asm("ex2.approx.f32 %0, %1;" : "=f"(corr0) : "f"(d0));
            asm("ex2.approx.f32 %0, %1;" : "=f"(corr1) : "f"(d1));
        }
        mrun0 = mnew0; mrun1 = mnew1;

        // ---- p = 2^(clamp(s - m)) via f16x2 MUFU; pack as PV A-fragments ----
        unsigned pf[8][2];
#pragma unroll
        for (int j = 0; j < 8; j++) {
            float y0 = fmaxf(p[j][0] - mnew0, YCLAMP);
            float y1 = fmaxf(p[j][1] - mnew0, YCLAMP);
            float y2 = fmaxf(p[j][2] - mnew1, YCLAMP);
            float y3 = fmaxf(p[j][3] - mnew1, YCLAMP);
            unsigned t0, t1;
            asm("cvt.rn.f16x2.f32 %0, %1, %2;" : "=r"(t0) : "f"(y1), "f"(y0));
            asm("cvt.rn.f16x2.f32 %0, %1, %2;" : "=r"(t1) : "f"(y3), "f"(y2));
            asm("ex2.approx.f16x2 %0, %0;" : "+r"(t0));
            asm("ex2.approx.f16x2 %0, %0;" : "+r"(t1));
            pf[j][0] = t0;
            pf[j][1] = t1;
            o[j][0] *= corr0; o[j][1] *= corr0;
            o[j][2] *= corr1; o[j][3] *= corr1;
        }

        // ---- O += P V (V 2-term split) ; l via ones-column MMA ----
        float ltmp[4] = {0.0f, 0.0f, 0.0f, 0.0f};
        const unsigned ones2[2] = {0x3C003C00u, 0x3C003C00u};
#pragma unroll
        for (int kc = 0; kc < 4; kc++) {
            unsigned pa[4] = {pf[2 * kc][0], pf[2 * kc][1],
                              pf[2 * kc + 1][0], pf[2 * kc + 1][1]};
            mma16816h(ltmp, pa, ones2);
#pragma unroll
            for (int j = 0; j < 8; j++) {
                int bbase = (j * 8 + g) * VSW + kc * 8 + tig;
                unsigned bh[2] = {VHI[bbase], VHI[bbase + 4]};
                unsigned bl[2] = {VLO[bbase], VLO[bbase + 4]};
                mma16816h(o[j], pa, bh);
                mma16816h(o[j], pa, bl);
            }
        }
        lrun0 = lrun0 * corr0 + ltmp[0];
        lrun1 = lrun1 * corr1 + ltmp[2];
    }

    // ---- normalize & write ctx [B,S,D] ----
    float inv0 = 1.0f / lrun0;
    float inv1 = 1.0f / lrun1;
#pragma unroll
    for (int j = 0; j < 8; j++) {
        int dh = j * 8 + 2 * tig;
        size_t r0 = ((size_t)b * SS + wrow + g) * DD + h * DH + dh;
        size_t r1 = ((size_t)b * SS + wrow + g + 8) * DD + h * DH + dh;
        *(float2*)&O[r0] = make_float2(o[j][0] * inv0, o[j][1] * inv0);
        *(float2*)&O[r1] = make_float2(o[j][2] * inv1, o[j][3] * inv1);
    }
}

// ---------------------------------------------------------------------------
// Launch
// ---------------------------------------------------------------------------
extern "C" void kernel_launch(void* const* d_in, const int* in_sizes, int n_in,
                              void* d_out, int out_size)
{
    const float* q  = (const float*)d_in[0];
    const float* k  = (const float*)d_in[1];
    const float* v  = (const float*)d_in[2];
    // d_in[3] = mask (causal tril; implemented analytically)
    const float* wq = (const float*)d_in[4];
    const float* bq = (const float*)d_in[5];
    const float* wk = (const float*)d_in[6];
    const float* bk = (const float*)d_in[7];
    const float* wv = (const float*)d_in[8];
    const float* bv = (const float*)d_in[9];
    const float* wo = (const float*)d_in[10];
    const float* bo = (const float*)d_in[11];
    float* out = (float*)d_out;

    float *Ctx;
    __half *Ahi, *Alo, *Whi, *Wlo;
    __half *Qhi, *Qlo, *Khi, *Klo, *Vhi, *Vlo;
    cudaGetSymbolAddress((void**)&Ctx, g_Ctx);
    cudaGetSymbolAddress((void**)&Ahi, g_Ahi);
    cudaGetSymbolAddress((void**)&Alo, g_Alo);
    cudaGetSymbolAddress((void**)&Whi, g_Whi);
    cudaGetSymbolAddress((void**)&Wlo, g_Wlo);
    cudaGetSymbolAddress((void**)&Qhi, g_Qhi);
    cudaGetSymbolAddress((void**)&Qlo, g_Qlo);
    cudaGetSymbolAddress((void**)&Khi, g_Khi);
    cudaGetSymbolAddress((void**)&Klo, g_Klo);
    cudaGetSymbolAddress((void**)&Vhi, g_Vhi);
    cudaGetSymbolAddress((void**)&Vlo, g_Vlo);

    cudaFuncSetAttribute(flash_attn_tc, cudaFuncAttributeMaxDynamicSharedMemorySize,
                         FA_SMEM);

    const int nA4 = (MM * DD) / 4;
    const int nW4 = (DD * DD) / 4;
    dim3 sa((nA4 + 255) / 256), sw((nW4 + 255) / 256);
    dim3 gg(DD / TBN, MM / TBM);        // (8, 64)

    const float qscale = 0.125f * 1.44269504088896f;  // 1/sqrt(DH) * log2(e)

    // Q projection -> split f16, pre-scaled for log2-domain softmax
    split_f16<<<sa, 256>>>(q,  Ahi, Alo, nA4);
    split_f16<<<sw, 256>>>(wq, Whi, Wlo, nW4);
    gemm_f16split<true><<<gg, 256>>>(Ahi, Alo, Whi, Wlo, bq, qscale,
                                     nullptr, Qhi, Qlo);
    // K projection
    split_f16<<<sa, 256>>>(k,  Ahi, Alo, nA4);
    split_f16<<<sw, 256>>>(wk, Whi, Wlo, nW4);
    gemm_f16split<true><<<gg, 256>>>(Ahi, Alo, Whi, Wlo, bk, 1.0f,
                                     nullptr, Khi, Klo);
    // V projection
    split_f16<<<sa, 256>>>(v,  Ahi, Alo, nA4);
    split_f16<<<sw, 256>>>(wv, Whi, Wlo, nW4);
    gemm_f16split<true><<<gg, 256>>>(Ahi, Alo, Whi, Wlo, bv, 1.0f,
                                     nullptr, Vhi, Vlo);

    // Attention
    dim3 fg(SS / 128, HH, BB);          // (16, 16, 4)
    flash_attn_tc<<<fg, 256, FA_SMEM>>>(Qhi, Qlo, Khi, Klo, Vhi, Vlo, Ctx);

    // Output projection (fp32 result)
    split_f16<<<sa, 256>>>(Ctx, Ahi, Alo, nA4);
    split_f16<<<sw, 256>>>(wo,  Whi, Wlo, nW4);
    gemm_f16split<false><<<gg, 256>>>(Ahi, Alo, Whi, Wlo, bo, 1.0f,
                                      out, nullptr, nullptr);
}

// round 7
// speedup vs baseline: 2.3320x; 1.0344x over previous
#include <cuda_runtime.h>
#include <cuda_fp16.h>
#include <math.h>

// Problem constants
#define BB 4
#define SS 2048
#define DD 1024
#define HH 16
#define DH 64
#define MM (BB * SS)   // 8192

#define MASKV  (-1e4f)   // finite mask sentinel (log2-domain scores are |s| <~ 30)
#define YCLAMP (-30.0f)  // 2^-30 underflows to 0 in f16 exp output

// ---------------------------------------------------------------------------
// Scratch (device globals)
// ---------------------------------------------------------------------------
__device__ __half g_Ahi[(size_t)MM * DD];
__device__ __half g_Alo[(size_t)MM * DD];
__device__ __half g_Whi[(size_t)DD * DD];
__device__ __half g_Wlo[(size_t)DD * DD];

__device__ __half g_Qhi[(size_t)MM * DD];
__device__ __half g_Qlo[(size_t)MM * DD];
__device__ __half g_Khi[(size_t)MM * DD];
__device__ __half g_Klo[(size_t)MM * DD];
__device__ __half g_Vhi[(size_t)MM * DD];   // V^T layout: [b][h][dh][s]
__device__ __half g_Vlo[(size_t)MM * DD];

// ---------------------------------------------------------------------------
// mma.sync m16n8k16 f16 -> fp32
// ---------------------------------------------------------------------------
__device__ __forceinline__ void mma16816h(float* c, const unsigned* a, const unsigned* b)
{
    asm volatile(
        "mma.sync.aligned.m16n8k16.row.col.f32.f16.f16.f32 "
        "{%0,%1,%2,%3}, {%4,%5,%6,%7}, {%8,%9}, {%0,%1,%2,%3};\n"
        : "+f"(c[0]), "+f"(c[1]), "+f"(c[2]), "+f"(c[3])
        : "r"(a[0]), "r"(a[1]), "r"(a[2]), "r"(a[3]), "r"(b[0]), "r"(b[1]));
}

__device__ __forceinline__ void split2h(float x, float y, unsigned& hi, unsigned& lo)
{
    __half hx = __float2half(x);
    __half hy = __float2half(y);
    float rx = x - __half2float(hx);
    float ry = y - __half2float(hy);
    __half2 H(hx, hy);
    __half2 L(__float2half(rx), __float2half(ry));
    hi = *(unsigned*)&H;
    lo = *(unsigned*)&L;
}

// cp.async helpers
__device__ __forceinline__ void cp16(unsigned saddr, const void* g)
{
    asm volatile("cp.async.cg.shared.global [%0], [%1], 16;\n" :: "r"(saddr), "l"(g));
}
__device__ __forceinline__ void cp_commit()
{
    asm volatile("cp.async.commit_group;\n");
}
template<int N> __device__ __forceinline__ void cp_wait()
{
    asm volatile("cp.async.wait_group %0;\n" :: "n"(N));
}

// ---------------------------------------------------------------------------
// Split fp32 -> f16 hi + lo (GEMM inputs)
// ---------------------------------------------------------------------------
__global__ __launch_bounds__(256) void split_f16(
    const float* __restrict__ X,
    __half* __restrict__ hi, __half* __restrict__ lo, int n4)
{
    int i = blockIdx.x * blockDim.x + threadIdx.x;
    if (i >= n4) return;
    float4 x = ((const float4*)X)[i];
    unsigned h0, l0, h1, l1;
    split2h(x.x, x.y, h0, l0);
    split2h(x.z, x.w, h1, l1);
    unsigned* H = (unsigned*)(hi + (size_t)i * 4);
    unsigned* L = (unsigned*)(lo + (size_t)i * 4);
    H[0] = h0; H[1] = h1;
    L[0] = l0; L[1] = l1;
}

// ---------------------------------------------------------------------------
// Split-f16 tensor-core GEMM:  C[m,n] = (sum_k A[m,k]*W[n,k] + bias[n])*scale
// MODE 0: fp32 C. MODE 1: f16 hi/lo row-major. MODE 2: f16 hi/lo transposed
//         into [b][h][dh][s] (for V^T).
// ---------------------------------------------------------------------------
#define TBM 128
#define TBN 128
#define TBK 32
#define TLDA 40          // halves per smem row (32 + 8 pad); 20 u32
#define NKT_G 96         // 3 * (1024/32)

template<int MODE>
__global__ __launch_bounds__(256, 2) void gemm_f16split(
    const __half* __restrict__ Ahi, const __half* __restrict__ Alo,
    const __half* __restrict__ Whi, const __half* __restrict__ Wlo,
    const float* __restrict__ bias, float scale,
    float* __restrict__ C, __half* __restrict__ Chi, __half* __restrict__ Clo)
{
    __shared__ __align__(16) __half As[TBM * TLDA];
    __shared__ __align__(16) __half Bs[TBN * TLDA];

    const int tid  = threadIdx.x;
    const int wid  = tid >> 5;
    const int lane = tid & 31;
    const int g    = lane >> 2;
    const int tig  = lane & 3;
    const int wr   = wid >> 2;
    const int wc   = wid & 3;
    const int m0   = blockIdx.y * TBM;
    const int n0   = blockIdx.x * TBN;

    const int r0 = (tid * 2) >> 2;
    const int o0 = ((tid * 2) & 3) * 8;
    const int r1 = (tid * 2 + 1) >> 2;
    const int o1 = ((tid * 2 + 1) & 3) * 8;

    const __half* Asegs[3] = {Ahi, Ahi, Alo};
    const __half* Wsegs[3] = {Whi, Wlo, Whi};

    float acc[4][4][4];
#pragma unroll
    for (int mt = 0; mt < 4; mt++)
#pragma unroll
        for (int nt = 0; nt < 4; nt++)
#pragma unroll
            for (int i = 0; i < 4; i++) acc[mt][nt][i] = 0.0f;

    uint4 pa0, pa1, pb0, pb1;
    {
        const __half* A = Asegs[0];
        const __half* W = Wsegs[0];
        pa0 = *(const uint4*)(A + (size_t)(m0 + r0) * DD + o0);
        pa1 = *(const uint4*)(A + (size_t)(m0 + r1) * DD + o1);
        pb0 = *(const uint4*)(W + (size_t)(n0 + r0) * DD + o0);
        pb1 = *(const uint4*)(W + (size_t)(n0 + r1) * DD + o1);
    }

    for (int kt = 0; kt < NKT_G; kt++) {
        *(uint4*)(As + r0 * TLDA + o0) = pa0;
        *(uint4*)(As + r1 * TLDA + o1) = pa1;
        *(uint4*)(Bs + r0 * TLDA + o0) = pb0;
        *(uint4*)(Bs + r1 * TLDA + o1) = pb1;
        __syncthreads();

        if (kt + 1 < NKT_G) {
            int seg = (kt + 1) >> 5;
            int k0  = ((kt + 1) & 31) * TBK;
            const __half* A = Asegs[seg];
            const __half* W = Wsegs[seg];
            pa0 = *(const uint4*)(A + (size_t)(m0 + r0) * DD + k0 + o0);
            pa1 = *(const uint4*)(A + (size_t)(m0 + r1) * DD + k0 + o1);
            pb0 = *(const uint4*)(W + (size_t)(n0 + r0) * DD + k0 + o0);
            pb1 = *(const uint4*)(W + (size_t)(n0 + r1) * DD + k0 + o1);
        }

        const unsigned* A32 = (const unsigned*)As;
        const unsigned* B32 = (const unsigned*)Bs;
#pragma unroll
        for (int ks = 0; ks < 2; ks++) {
            unsigned af[4][4], bf[4][2];
#pragma unroll
            for (int mt = 0; mt < 4; mt++) {
                int base = (wr * 64 + mt * 16 + g) * 20 + ks * 8 + tig;
                af[mt][0] = A32[base];
                af[mt][1] = A32[base + 8 * 20];
                af[mt][2] = A32[base + 4];
                af[mt][3] = A32[base + 8 * 20 + 4];
            }
#pragma unroll
            for (int nt = 0; nt < 4; nt++) {
                int base = (wc * 32 + nt * 8 + g) * 20 + ks * 8 + tig;
                bf[nt][0] = B32[base];
                bf[nt][1] = B32[base + 4];
            }
#pragma unroll
            for (int mt = 0; mt < 4; mt++)
#pragma unroll
                for (int nt = 0; nt < 4; nt++)
                    mma16816h(acc[mt][nt], af[mt], bf[nt]);
        }
        __syncthreads();
    }

#pragma unroll
    for (int mt = 0; mt < 4; mt++) {
        int row = m0 + wr * 64 + mt * 16 + g;
#pragma unroll
        for (int nt = 0; nt < 4; nt++) {
            int col = n0 + wc * 32 + nt * 8 + 2 * tig;
            float b0 = bias[col], b1 = bias[col + 1];
            float v0 = (acc[mt][nt][0] + b0) * scale;
            float v1 = (acc[mt][nt][1] + b1) * scale;
            float v2 = (acc[mt][nt][2] + b0) * scale;
            float v3 = (acc[mt][nt][3] + b1) * scale;
            if (MODE == 0) {
                *(float2*)&C[(size_t)row * DD + col] = make_float2(v0, v1);
                *(float2*)&C[(size_t)(row + 8) * DD + col] = make_float2(v2, v3);
            } else if (MODE == 1) {
                unsigned h01, l01, h23, l23;
                split2h(v0, v1, h01, l01);
                split2h(v2, v3, h23, l23);
                *(unsigned*)(Chi + (size_t)row * DD + col) = h01;
                *(unsigned*)(Clo + (size_t)row * DD + col) = l01;
                *(unsigned*)(Chi + (size_t)(row + 8) * DD + col) = h23;
                *(unsigned*)(Clo + (size_t)(row + 8) * DD + col) = l23;
            } else {
                // transposed V^T: dst[((b*HH+h)*DH+dh)*SS + s]
                float vv[4] = {v0, v1, v2, v3};
                int rr[4] = {row, row, row + 8, row + 8};
                int cc[4] = {col, col + 1, col, col + 1};
#pragma unroll
                for (int e = 0; e < 4; e++) {
                    int bq = rr[e] >> 11, s = rr[e] & 2047;
                    int hh = cc[e] >> 6,  dh = cc[e] & 63;
                    size_t di = (((size_t)bq * HH + hh) * DH + dh) * SS + s;
                    __half hx = __float2half(vv[e]);
                    Chi[di] = hx;
                    Clo[di] = __float2half(vv[e] - __half2float(hx));
                }
            }
        }
    }
}

// ---------------------------------------------------------------------------
// Pipelined tensor-core causal flash attention.
// Grid: (S/128, H, B). Block: 256 threads (8 warps), warp w = q rows [16w,16w+16).
// K/V tiles of 64 keys, cp.async double-buffered; V pre-transposed globally.
// smem (bytes): QHI 0 (18432) | QLO 18432 | Kbuf{0,1} @36864+buf*18432
//               (hi, lo=+9216) | Vbuf{0,1} @73728+buf*18432. Total 110592.
// Row stride: 72 halves = 36 u32 = 144 B everywhere.
// ---------------------------------------------------------------------------
#define FA_SMEM 110592
#define STR 36   // u32 stride per smem row

__global__ __launch_bounds__(256) void flash_attn_tc(
    const __half* __restrict__ Qhi_, const __half* __restrict__ Qlo_,
    const __half* __restrict__ Khi_, const __half* __restrict__ Klo_,
    const __half* __restrict__ VhiT_, const __half* __restrict__ VloT_,
    __half* __restrict__ CtxHi, __half* __restrict__ CtxLo)
{
    extern __shared__ __align__(16) char smraw[];
    const unsigned sbase = (unsigned)__cvta_generic_to_shared(smraw);

    const int tid  = threadIdx.x;
    const int w    = tid >> 5;
    const int lane = tid & 31;
    const int g    = lane >> 2;
    const int tig  = lane & 3;
    const int qt   = blockIdx.x;
    const int h    = blockIdx.y;
    const int b    = blockIdx.z;
    const int s0   = qt * 128;

    const size_t base   = ((size_t)b * SS) * DD + (size_t)h * DH;
    const size_t vtbase = ((size_t)(b * HH + h)) * DH * SS;

    const int wrow = s0 + w * 16;
    const int nkt  = 2 * (qt + 1);

    // ---- Q fill via cp.async (8 x 16B per thread) ----
    {
        int row = tid >> 1, hf = tid & 1;
        const __half* srcH = Qhi_ + base + (size_t)(s0 + row) * DD + hf * 32;
        const __half* srcL = Qlo_ + base + (size_t)(s0 + row) * DD + hf * 32;
        unsigned dH = sbase + (row * STR + hf * 16) * 4;
        unsigned dL = dH + 18432;
#pragma unroll
        for (int j = 0; j < 4; j++) {
            cp16(dH + j * 16, srcH + j * 8);
            cp16(dL + j * 16, srcL + j * 8);
        }
    }

    // tile fill: 8 x 16B per thread (K hi/lo + V hi/lo)
    const int frow = tid >> 2;       // 0..63
    const int fc   = tid & 3;        // chunks fc and fc+4
    auto fillKV = [&](int buf, int c0) {
        size_t kro = base + (size_t)(c0 + frow) * DD;
        unsigned kH = sbase + 36864 + buf * 18432 + frow * 144;
        unsigned kL = kH + 9216;
        cp16(kH + fc * 16,       Khi_ + kro + fc * 8);
        cp16(kH + (fc + 4) * 16, Khi_ + kro + (fc + 4) * 8);
        cp16(kL + fc * 16,       Klo_ + kro + fc * 8);
        cp16(kL + (fc + 4) * 16, Klo_ + kro + (fc + 4) * 8);
        size_t vro = vtbase + (size_t)frow * SS + c0;
        unsigned vH = sbase + 73728 + buf * 18432 + frow * 144;
        unsigned vL = vH + 9216;
        cp16(vH + fc * 16,       VhiT_ + vro + fc * 8);
        cp16(vH + (fc + 4) * 16, VhiT_ + vro + (fc + 4) * 8);
        cp16(vL + fc * 16,       VloT_ + vro + fc * 8);
        cp16(vL + (fc + 4) * 16, VloT_ + vro + (fc + 4) * 8);
    };

    // prologue: group0 = Q + tile0 ; group1 = tile1 (or empty)
    fillKV(0, 0);
    cp_commit();
    if (nkt > 1) fillKV(1, 64);
    cp_commit();

    float o[8][4];
    float mrun0 = MASKV, mrun1 = MASKV;
    float lrun0 = 0.0f,  lrun1 = 0.0f;
#pragma unroll
    for (int j = 0; j < 8; j++)
#pragma unroll
        for (int e = 0; e < 4; e++) o[j][e] = 0.0f;

    const unsigned* QHI = (const unsigned*)smraw;
    const unsigned* QLO = QHI + 4608;

    for (int kt = 0; kt < nkt; kt++) {
        const int c0 = kt * 64;
        if (kt + 1 < nkt) cp_wait<1>(); else cp_wait<0>();
        __syncthreads();

        const unsigned* KHI = (const unsigned*)(smraw + 36864 + (kt & 1) * 18432);
        const unsigned* KLO = KHI + 2304;
        const unsigned* VHI = (const unsigned*)(smraw + 73728 + (kt & 1) * 18432);
        const unsigned* VLO = VHI + 2304;

        if (c0 <= wrow + 15) {
            // ---- S = Q K^T (3-term f16 split; log2 domain) ----
            float p[8][4];
#pragma unroll
            for (int j = 0; j < 8; j++)
#pragma unroll
                for (int e = 0; e < 4; e++) p[j][e] = 0.0f;

#pragma unroll
            for (int kc = 0; kc < 4; kc++) {
                int abase = (w * 16 + g) * STR + kc * 8 + tig;
                unsigned ah[4], al[4];
                ah[0] = QHI[abase];           ah[1] = QHI[abase + 8 * STR];
                ah[2] = QHI[abase + 4];       ah[3] = QHI[abase + 8 * STR + 4];
                al[0] = QLO[abase];           al[1] = QLO[abase + 8 * STR];
                al[2] = QLO[abase + 4];       al[3] = QLO[abase + 8 * STR + 4];
#pragma unroll
                for (int j = 0; j < 8; j++) {
                    int bbase = (j * 8 + g) * STR + kc * 8 + tig;
                    unsigned bh[2] = {KHI[bbase], KHI[bbase + 4]};
                    unsigned bl[2] = {KLO[bbase], KLO[bbase + 4]};
                    mma16816h(p[j], ah, bh);
                    mma16816h(p[j], ah, bl);
                    mma16816h(p[j], al, bh);
                }
            }

            // ---- causal mask ----
            if (c0 + 63 > wrow) {
                int r0 = wrow + g, r1 = wrow + g + 8;
#pragma unroll
                for (int j = 0; j < 8; j++) {
                    int cA = c0 + j * 8 + 2 * tig;
                    if (cA     > r0) p[j][0] = MASKV;
                    if (cA + 1 > r0) p[j][1] = MASKV;
                    if (cA     > r1) p[j][2] = MASKV;
                    if (cA + 1 > r1) p[j][3] = MASKV;
                }
            }

            // ---- row max ----
            float mt0 = MASKV, mt1 = MASKV;
#pragma unroll
            for (int j = 0; j < 8; j++) {
                mt0 = fmaxf(mt0, fmaxf(p[j][0], p[j][1]));
                mt1 = fmaxf(mt1, fmaxf(p[j][2], p[j][3]));
            }
            mt0 = fmaxf(mt0, __shfl_xor_sync(0xffffffffu, mt0, 1));
            mt0 = fmaxf(mt0, __shfl_xor_sync(0xffffffffu, mt0, 2));
            mt1 = fmaxf(mt1, __shfl_xor_sync(0xffffffffu, mt1, 1));
            mt1 = fmaxf(mt1, __shfl_xor_sync(0xffffffffu, mt1, 2));

            float mnew0 = fmaxf(mrun0, mt0);
            float mnew1 = fmaxf(mrun1, mt1);
            float corr0, corr1;
            {
                float d0 = fmaxf(mrun0 - mnew0, -126.0f);
                float d1 = fmaxf(mrun1 - mnew1, -126.0f);
                asm("ex2.approx.f32 %0, %1;" : "=f"(corr0) : "f"(d0));
                asm("ex2.approx.f32 %0, %1;" : "=f"(corr1) : "f"(d1));
            }
            mrun0 = mnew0; mrun1 = mnew1;

            // ---- p = 2^(clamp(s-m)) via f16x2 MUFU ----
            unsigned pf[8][2];
#pragma unroll
            for (int j = 0; j < 8; j++) {
                float y0 = fmaxf(p[j][0] - mnew0, YCLAMP);
                float y1 = fmaxf(p[j][1] - mnew0, YCLAMP);
                float y2 = fmaxf(p[j][2] - mnew1, YCLAMP);
                float y3 = fmaxf(p[j][3] - mnew1, YCLAMP);
                unsigned t0, t1;
                asm("cvt.rn.f16x2.f32 %0, %1, %2;" : "=r"(t0) : "f"(y1), "f"(y0));
                asm("cvt.rn.f16x2.f32 %0, %1, %2;" : "=r"(t1) : "f"(y3), "f"(y2));
                asm("ex2.approx.f16x2 %0, %0;" : "+r"(t0));
                asm("ex2.approx.f16x2 %0, %0;" : "+r"(t1));
                pf[j][0] = t0;
                pf[j][1] = t1;
                o[j][0] *= corr0; o[j][1] *= corr0;
                o[j][2] *= corr1; o[j][3] *= corr1;
            }

            // ---- O += P V (V 2-term split); l via ones-column MMA ----
            float ltmp[4] = {0.0f, 0.0f, 0.0f, 0.0f};
            const unsigned ones2[2] = {0x3C003C00u, 0x3C003C00u};
#pragma unroll
            for (int kc = 0; kc < 4; kc++) {
                unsigned pa[4] = {pf[2 * kc][0], pf[2 * kc][1],
                                  pf[2 * kc + 1][0], pf[2 * kc + 1][1]};
                mma16816h(ltmp, pa, ones2);
#pragma unroll
                for (int j = 0; j < 8; j++) {
                    int bbase = (j * 8 + g) * STR + kc * 8 + tig;
                    unsigned bh[2] = {VHI[bbase], VHI[bbase + 4]};
                    unsigned bl[2] = {VLO[bbase], VLO[bbase + 4]};
                    mma16816h(o[j], pa, bh);
                    mma16816h(o[j], pa, bl);
                }
            }
            lrun0 = lrun0 * corr0 + ltmp[0];
            lrun1 = lrun1 * corr1 + ltmp[2];
        }

        __syncthreads();
        if (kt + 2 < nkt) {
            fillKV(kt & 1, c0 + 128);
            cp_commit();
        }
    }

    // ---- normalize & write split ctx [B,S,D] ----
    float inv0 = 1.0f / lrun0;
    float inv1 = 1.0f / lrun1;
#pragma unroll
    for (int j = 0; j < 8; j++) {
        int dh = j * 8 + 2 * tig;
        size_t r0 = ((size_t)b * SS + wrow + g) * DD + h * DH + dh;
        size_t r1 = ((size_t)b * SS + wrow + g + 8) * DD + h * DH + dh;
        unsigned h0, l0, h1, l1;
        split2h(o[j][0] * inv0, o[j][1] * inv0, h0, l0);
        split2h(o[j][2] * inv1, o[j][3] * inv1, h1, l1);
        *(unsigned*)(CtxHi + r0) = h0;
        *(unsigned*)(CtxLo + r0) = l0;
        *(unsigned*)(CtxHi + r1) = h1;
        *(unsigned*)(CtxLo + r1) = l1;
    }
}

// ---------------------------------------------------------------------------
// Launch
// ---------------------------------------------------------------------------
extern "C" void kernel_launch(void* const* d_in, const int* in_sizes, int n_in,
                              void* d_out, int out_size)
{
    const float* q  = (const float*)d_in[0];
    const float* k  = (const float*)d_in[1];
    const float* v  = (const float*)d_in[2];
    // d_in[3] = mask (causal tril; implemented analytically)
    const float* wq = (const float*)d_in[4];
    const float* bq = (const float*)d_in[5];
    const float* wk = (const float*)d_in[6];
    const float* bk = (const float*)d_in[7];
    const float* wv = (const float*)d_in[8];
    const float* bv = (const float*)d_in[9];
    const float* wo = (const float*)d_in[10];
    const float* bo = (const float*)d_in[11];
    float* out = (float*)d_out;

    __half *Ahi, *Alo, *Whi, *Wlo;
    __half *Qhi, *Qlo, *Khi, *Klo, *Vhi, *Vlo;
    cudaGetSymbolAddress((void**)&Ahi, g_Ahi);
    cudaGetSymbolAddress((void**)&Alo, g_Alo);
    cudaGetSymbolAddress((void**)&Whi, g_Whi);
    cudaGetSymbolAddress((void**)&Wlo, g_Wlo);
    cudaGetSymbolAddress((void**)&Qhi, g_Qhi);
    cudaGetSymbolAddress((void**)&Qlo, g_Qlo);
    cudaGetSymbolAddress((void**)&Khi, g_Khi);
    cudaGetSymbolAddress((void**)&Klo, g_Klo);
    cudaGetSymbolAddress((void**)&Vhi, g_Vhi);
    cudaGetSymbolAddress((void**)&Vlo, g_Vlo);

    cudaFuncSetAttribute(flash_attn_tc, cudaFuncAttributeMaxDynamicSharedMemorySize,
                         FA_SMEM);

    const int nA4 = (MM * DD) / 4;
    const int nW4 = (DD * DD) / 4;
    dim3 sa((nA4 + 255) / 256), sw((nW4 + 255) / 256);
    dim3 gg(DD / TBN, MM / TBM);        // (8, 64)

    const float qscale = 0.125f * 1.44269504088896f;  // 1/sqrt(DH) * log2(e)

    // Q projection -> split f16 rows, pre-scaled for log2-domain softmax
    split_f16<<<sa, 256>>>(q,  Ahi, Alo, nA4);
    split_f16<<<sw, 256>>>(wq, Whi, Wlo, nW4);
    gemm_f16split<1><<<gg, 256>>>(Ahi, Alo, Whi, Wlo, bq, qscale,
                                  nullptr, Qhi, Qlo);
    // K projection
    split_f16<<<sa, 256>>>(k,  Ahi, Alo, nA4);
    split_f16<<<sw, 256>>>(wk, Whi, Wlo, nW4);
    gemm_f16split<1><<<gg, 256>>>(Ahi, Alo, Whi, Wlo, bk, 1.0f,
                                  nullptr, Khi, Klo);
    // V projection -> transposed split output [b][h][dh][s]
    split_f16<<<sa, 256>>>(v,  Ahi, Alo, nA4);
    split_f16<<<sw, 256>>>(wv, Whi, Wlo, nW4);
    gemm_f16split<2><<<gg, 256>>>(Ahi, Alo, Whi, Wlo, bv, 1.0f,
                                  nullptr, Vhi, Vlo);

    // Attention -> split ctx directly into Ahi/Alo
    dim3 fg(SS / 128, HH, BB);          // (16, 16, 4)
    flash_attn_tc<<<fg, 256, FA_SMEM>>>(Qhi, Qlo, Khi, Klo, Vhi, Vlo, Ahi, Alo);

    // Output projection (fp32 result)
    split_f16<<<sw, 256>>>(wo, Whi, Wlo, nW4);
    gemm_f16split<0><<<gg, 256>>>(Ahi, Alo, Whi, Wlo, bo, 1.0f,
                                  out, nullptr, nullptr);
}

// round 9
// speedup vs baseline: 2.9280x; 1.2555x over previous
#include <cuda_runtime.h>
#include <cuda_fp16.h>
#include <math.h>

// Problem constants
#define BB 4
#define SS 2048
#define DD 1024
#define HH 16
#define DH 64
#define MM (BB * SS)   // 8192

#define MASKV  (-1e4f)
#define YCLAMP (-30.0f)

// ---------------------------------------------------------------------------
// Scratch (device globals)
// ---------------------------------------------------------------------------
__device__ __half g_ActHi[(size_t)3 * MM * DD];   // q/k/v splits; plane0 reused for ctx
__device__ __half g_ActLo[(size_t)3 * MM * DD];
__device__ __half g_WHi[(size_t)4 * DD * DD];     // wq, wk, wv, wo
__device__ __half g_WLo[(size_t)4 * DD * DD];

__device__ __half g_Qhi[(size_t)MM * DD];
__device__ __half g_Qlo[(size_t)MM * DD];
__device__ __half g_Khi[(size_t)MM * DD];
__device__ __half g_Klo[(size_t)MM * DD];
__device__ __half g_Vhi[(size_t)MM * DD];   // V^T layout: [b][h][dh][s]
__device__ __half g_Vlo[(size_t)MM * DD];

// ---------------------------------------------------------------------------
// mma.sync m16n8k16 f16 -> fp32
// ---------------------------------------------------------------------------
__device__ __forceinline__ void mma16816h(float* c, const unsigned* a, const unsigned* b)
{
    asm volatile(
        "mma.sync.aligned.m16n8k16.row.col.f32.f16.f16.f32 "
        "{%0,%1,%2,%3}, {%4,%5,%6,%7}, {%8,%9}, {%0,%1,%2,%3};\n"
        : "+f"(c[0]), "+f"(c[1]), "+f"(c[2]), "+f"(c[3])
        : "r"(a[0]), "r"(a[1]), "r"(a[2]), "r"(a[3]), "r"(b[0]), "r"(b[1]));
}

__device__ __forceinline__ void split2h(float x, float y, unsigned& hi, unsigned& lo)
{
    __half hx = __float2half(x);
    __half hy = __float2half(y);
    float rx = x - __half2float(hx);
    float ry = y - __half2float(hy);
    __half2 H(hx, hy);
    __half2 L(__float2half(rx), __float2half(ry));
    hi = *(unsigned*)&H;
    lo = *(unsigned*)&L;
}

// cp.async helpers
__device__ __forceinline__ void cp16(unsigned saddr, const void* g)
{
    asm volatile("cp.async.cg.shared.global [%0], [%1], 16;\n" :: "r"(saddr), "l"(g));
}
__device__ __forceinline__ void cp_commit()
{
    asm volatile("cp.async.commit_group;\n");
}
template<int N> __device__ __forceinline__ void cp_wait()
{
    asm volatile("cp.async.wait_group %0;\n" :: "n"(N));
}

// ---------------------------------------------------------------------------
// Batched splits: activations (q,k,v) and weights (wq,wk,wv,wo)
// ---------------------------------------------------------------------------
__device__ __forceinline__ void split_store(const float* X, __half* hi, __half* lo, int i)
{
    float4 x = ((const float4*)X)[i];
    unsigned h0, l0, h1, l1;
    split2h(x.x, x.y, h0, l0);
    split2h(x.z, x.w, h1, l1);
    unsigned* H = (unsigned*)(hi + (size_t)i * 4);
    unsigned* L = (unsigned*)(lo + (size_t)i * 4);
    H[0] = h0; H[1] = h1;
    L[0] = l0; L[1] = l1;
}

__global__ __launch_bounds__(256) void split_acts(
    const float* __restrict__ q, const float* __restrict__ k,
    const float* __restrict__ v, __half* __restrict__ hi, __half* __restrict__ lo)
{
    int i = blockIdx.x * blockDim.x + threadIdx.x;
    int n4 = (MM * DD) / 4;
    if (i >= n4) return;
    int z = blockIdx.y;
    const float* src = (z == 0) ? q : (z == 1) ? k : v;
    split_store(src, hi + (size_t)z * MM * DD, lo + (size_t)z * MM * DD, i);
}

__global__ __launch_bounds__(256) void split_wts(
    const float* __restrict__ w0, const float* __restrict__ w1,
    const float* __restrict__ w2, const float* __restrict__ w3,
    __half* __restrict__ hi, __half* __restrict__ lo)
{
    int i = blockIdx.x * blockDim.x + threadIdx.x;
    int n4 = (DD * DD) / 4;
    if (i >= n4) return;
    int z = blockIdx.y;
    const float* src = (z == 0) ? w0 : (z == 1) ? w1 : (z == 2) ? w2 : w3;
    split_store(src, hi + (size_t)z * DD * DD, lo + (size_t)z * DD * DD, i);
}

// ---------------------------------------------------------------------------
// Split-f16 tensor-core GEMM v2:
//   C[m,n] = (sum_k A[m,k]*W[n,k] + bias[n]) * scale
// BM=256, BN=128, BK=16, 512 threads (16 warps, warp tile 64x32).
// All 4 split arrays staged per k-chunk; 3 MMA combos per staging.
// 2-stage cp.async pipeline. Dynamic smem 73728 B.
// MODE 0: fp32 C. MODE 1: f16 hi/lo row-major. MODE 2: f16 hi/lo V^T.
// ---------------------------------------------------------------------------
#define GBM 256
#define GBN 128
#define GSTR 12          // u32 per smem row (16 halves + 8 pad = 24 h)
#define GBUF 36864       // bytes per stage: A 2*12288 + W 2*6144
#define G_ALO 12288
#define G_WHI 24576
#define G_WLO 30720
#define G_SMEM (2 * GBUF)

template<int MODE>
__global__ __launch_bounds__(512) void gemm_f16split(
    const __half* __restrict__ Ahi, const __half* __restrict__ Alo,
    const __half* __restrict__ Whi, const __half* __restrict__ Wlo,
    const float* __restrict__ bias, float scale,
    float* __restrict__ C, __half* __restrict__ Chi, __half* __restrict__ Clo)
{
    extern __shared__ __align__(16) char gsm[];
    const unsigned sbase = (unsigned)__cvta_generic_to_shared(gsm);

    const int tid  = threadIdx.x;
    const int wid  = tid >> 5;
    const int lane = tid & 31;
    const int g    = lane >> 2;
    const int tig  = lane & 3;
    const int wr   = wid >> 2;    // 0..3 : 64-row group
    const int wc   = wid & 3;     // 0..3 : 32-col group
    const int m0   = blockIdx.y * GBM;
    const int n0   = blockIdx.x * GBN;

    float acc[4][4][4];
#pragma unroll
    for (int mt = 0; mt < 4; mt++)
#pragma unroll
        for (int nt = 0; nt < 4; nt++)
#pragma unroll
            for (int i = 0; i < 4; i++) acc[mt][nt][i] = 0.0f;

    const int ar = tid >> 1, ac = (tid & 1) * 8;        // A: 512 chunks
    auto fill = [&](int buf, int kt) {
        int k0 = kt * 16;
        unsigned sb = sbase + buf * GBUF;
        size_t aro = (size_t)(m0 + ar) * DD + k0 + ac;
        cp16(sb + ar * 48 + ac * 2,          Ahi + aro);
        cp16(sb + G_ALO + ar * 48 + ac * 2,  Alo + aro);
        if (tid < 256) {
            size_t wro = (size_t)(n0 + ar) * DD + k0 + ac;
            cp16(sb + G_WHI + ar * 48 + ac * 2, Whi + wro);
            cp16(sb + G_WLO + ar * 48 + ac * 2, Wlo + wro);
        }
    };

    fill(0, 0); cp_commit();
    fill(1, 1); cp_commit();

    for (int kt = 0; kt < 64; kt++) {
        cp_wait<1>();
        __syncthreads();

        const unsigned* AH = (const unsigned*)(gsm + (kt & 1) * GBUF);
        const unsigned* AL = AH + 3072;
        const unsigned* WH = AH + 6144;
        const unsigned* WL = AH + 7680;

        unsigned af[4][4], bh[4][2], bl[4][2];
        // A-hi fragments
#pragma unroll
        for (int mt = 0; mt < 4; mt++) {
            int base = (wr * 64 + mt * 16 + g) * GSTR + tig;
            af[mt][0] = AH[base];
            af[mt][1] = AH[base + 8 * GSTR];
            af[mt][2] = AH[base + 4];
            af[mt][3] = AH[base + 8 * GSTR + 4];
        }
        // W-hi fragments
#pragma unroll
        for (int nt = 0; nt < 4; nt++) {
            int base = (wc * 32 + nt * 8 + g) * GSTR + tig;
            bh[nt][0] = WH[base];
            bh[nt][1] = WH[base + 4];
        }
        // hi * hi
#pragma unroll
        for (int mt = 0; mt < 4; mt++)
#pragma unroll
            for (int nt = 0; nt < 4; nt++)
                mma16816h(acc[mt][nt], af[mt], bh[nt]);
        // W-lo fragments; hi * lo
#pragma unroll
        for (int nt = 0; nt < 4; nt++) {
            int base = (wc * 32 + nt * 8 + g) * GSTR + tig;
            bl[nt][0] = WL[base];
            bl[nt][1] = WL[base + 4];
        }
#pragma unroll
        for (int mt = 0; mt < 4; mt++)
#pragma unroll
            for (int nt = 0; nt < 4; nt++)
                mma16816h(acc[mt][nt], af[mt], bl[nt]);
        // A-lo fragments (overwrite af); lo * hi
#pragma unroll
        for (int mt = 0; mt < 4; mt++) {
            int base = (wr * 64 + mt * 16 + g) * GSTR + tig;
            af[mt][0] = AL[base];
            af[mt][1] = AL[base + 8 * GSTR];
            af[mt][2] = AL[base + 4];
            af[mt][3] = AL[base + 8 * GSTR + 4];
        }
#pragma unroll
        for (int mt = 0; mt < 4; mt++)
#pragma unroll
            for (int nt = 0; nt < 4; nt++)
                mma16816h(acc[mt][nt], af[mt], bh[nt]);

        __syncthreads();
        if (kt + 2 < 64) {
            fill(kt & 1, kt + 2);
            cp_commit();
        }
    }

    // Epilogue
#pragma unroll
    for (int mt = 0; mt < 4; mt++) {
        int row = m0 + wr * 64 + mt * 16 + g;
#pragma unroll
        for (int nt = 0; nt < 4; nt++) {
            int col = n0 + wc * 32 + nt * 8 + 2 * tig;
            float b0 = bias[col], b1 = bias[col + 1];
            float v0 = (acc[mt][nt][0] + b0) * scale;
            float v1 = (acc[mt][nt][1] + b1) * scale;
            float v2 = (acc[mt][nt][2] + b0) * scale;
            float v3 = (acc[mt][nt][3] + b1) * scale;
            if (MODE == 0) {
                *(float2*)&C[(size_t)row * DD + col] = make_float2(v0, v1);
                *(float2*)&C[(size_t)(row + 8) * DD + col] = make_float2(v2, v3);
            } else if (MODE == 1) {
                unsigned h01, l01, h23, l23;
                split2h(v0, v1, h01, l01);
                split2h(v2, v3, h23, l23);
                *(unsigned*)(Chi + (size_t)row * DD + col) = h01;
                *(unsigned*)(Clo + (size_t)row * DD + col) = l01;
                *(unsigned*)(Chi + (size_t)(row + 8) * DD + col) = h23;
                *(unsigned*)(Clo + (size_t)(row + 8) * DD + col) = l23;
            } else {
                float vv[4] = {v0, v1, v2, v3};
                int rr[4] = {row, row, row + 8, row + 8};
                int cc[4] = {col, col + 1, col, col + 1};
#pragma unroll
                for (int e = 0; e < 4; e++) {
                    int bq = rr[e] >> 11, s = rr[e] & 2047;
                    int hh = cc[e] >> 6,  dh = cc[e] & 63;
                    size_t di = (((size_t)bq * HH + hh) * DH + dh) * SS + s;
                    __half hx = __float2half(vv[e]);
                    Chi[di] = hx;
                    Clo[di] = __float2half(vv[e] - __half2float(hx));
                }
            }
        }
    }
}

// ---------------------------------------------------------------------------
// Pipelined tensor-core causal flash attention (unchanged from round 6).
// ---------------------------------------------------------------------------
#define FA_SMEM 110592
#define STR 36

__global__ __launch_bounds__(256) void flash_attn_tc(
    const __half* __restrict__ Qhi_, const __half* __restrict__ Qlo_,
    const __half* __restrict__ Khi_, const __half* __restrict__ Klo_,
    const __half* __restrict__ VhiT_, const __half* __restrict__ VloT_,
    __half* __restrict__ CtxHi, __half* __restrict__ CtxLo)
{
    extern __shared__ __align__(16) char smraw[];
    const unsigned sbase = (unsigned)__cvta_generic_to_shared(smraw);

    const int tid  = threadIdx.x;
    const int w    = tid >> 5;
    const int lane = tid & 31;
    const int g    = lane >> 2;
    const int tig  = lane & 3;
    const int qt   = blockIdx.x;
    const int h    = blockIdx.y;
    const int b    = blockIdx.z;
    const int s0   = qt * 128;

    const size_t base   = ((size_t)b * SS) * DD + (size_t)h * DH;
    const size_t vtbase = ((size_t)(b * HH + h)) * DH * SS;

    const int wrow = s0 + w * 16;
    const int nkt  = 2 * (qt + 1);

    {
        int row = tid >> 1, hf = tid & 1;
        const __half* srcH = Qhi_ + base + (size_t)(s0 + row) * DD + hf * 32;
        const __half* srcL = Qlo_ + base + (size_t)(s0 + row) * DD + hf * 32;
        unsigned dH = sbase + (row * STR + hf * 16) * 4;
        unsigned dL = dH + 18432;
#pragma unroll
        for (int j = 0; j < 4; j++) {
            cp16(dH + j * 16, srcH + j * 8);
            cp16(dL + j * 16, srcL + j * 8);
        }
    }

    const int frow = tid >> 2;
    const int fc   = tid & 3;
    auto fillKV = [&](int buf, int c0) {
        size_t kro = base + (size_t)(c0 + frow) * DD;
        unsigned kH = sbase + 36864 + buf * 18432 + frow * 144;
        unsigned kL = kH + 9216;
        cp16(kH + fc * 16,       Khi_ + kro + fc * 8);
        cp16(kH + (fc + 4) * 16, Khi_ + kro + (fc + 4) * 8);
        cp16(kL + fc * 16,       Klo_ + kro + fc * 8);
        cp16(kL + (fc + 4) * 16, Klo_ + kro + (fc + 4) * 8);
        size_t vro = vtbase + (size_t)frow * SS + c0;
        unsigned vH = sbase + 73728 + buf * 18432 + frow * 144;
        unsigned vL = vH + 9216;
        cp16(vH + fc * 16,       VhiT_ + vro + fc * 8);
        cp16(vH + (fc + 4) * 16, VhiT_ + vro + (fc + 4) * 8);
        cp16(vL + fc * 16,       VloT_ + vro + fc * 8);
        cp16(vL + (fc + 4) * 16, VloT_ + vro + (fc + 4) * 8);
    };

    fillKV(0, 0);
    cp_commit();
    if (nkt > 1) fillKV(1, 64);
    cp_commit();

    float o[8][4];
    float mrun0 = MASKV, mrun1 = MASKV;
    float lrun0 = 0.0f,  lrun1 = 0.0f;
#pragma unroll
    for (int j = 0; j < 8; j++)
#pragma unroll
        for (int e = 0; e < 4; e++) o[j][e] = 0.0f;

    const unsigned* QHI = (const unsigned*)smraw;
    const unsigned* QLO = QHI + 4608;

    for (int kt = 0; kt < nkt; kt++) {
        const int c0 = kt * 64;
        if (kt + 1 < nkt) cp_wait<1>(); else cp_wait<0>();
        __syncthreads();

        const unsigned* KHI = (const unsigned*)(smraw + 36864 + (kt & 1) * 18432);
        const unsigned* KLO = KHI + 2304;
        const unsigned* VHI = (const unsigned*)(smraw + 73728 + (kt & 1) * 18432);
        const unsigned* VLO = VHI + 2304;

        if (c0 <= wrow + 15) {
            float p[8][4];
#pragma unroll
            for (int j = 0; j < 8; j++)
#pragma unroll
                for (int e = 0; e < 4; e++) p[j][e] = 0.0f;

#pragma unroll
            for (int kc = 0; kc < 4; kc++) {
                int abase = (w * 16 + g) * STR + kc * 8 + tig;
                unsigned ah[4], al[4];
                ah[0] = QHI[abase];           ah[1] = QHI[abase + 8 * STR];
                ah[2] = QHI[abase + 4];       ah[3] = QHI[abase + 8 * STR + 4];
                al[0] = QLO[abase];           al[1] = QLO[abase + 8 * STR];
                al[2] = QLO[abase + 4];       al[3] = QLO[abase + 8 * STR + 4];
#pragma unroll
                for (int j = 0; j < 8; j++) {
                    int bbase = (j * 8 + g) * STR + kc * 8 + tig;
                    unsigned bh[2] = {KHI[bbase], KHI[bbase + 4]};
                    unsigned bl[2] = {KLO[bbase], KLO[bbase + 4]};
                    mma16816h(p[j], ah, bh);
                    mma16816h(p[j], ah, bl);
                    mma16816h(p[j], al, bh);
                }
            }

            if (c0 + 63 > wrow) {
                int r0 = wrow + g, r1 = wrow + g + 8;
#pragma unroll
                for (int j = 0; j < 8; j++) {
                    int cA = c0 + j * 8 + 2 * tig;
                    if (cA     > r0) p[j][0] = MASKV;
                    if (cA + 1 > r0) p[j][1] = MASKV;
                    if (cA     > r1) p[j][2] = MASKV;
                    if (cA + 1 > r1) p[j][3] = MASKV;
                }
            }

            float mt0 = MASKV, mt1 = MASKV;
#pragma unroll
            for (int j = 0; j < 8; j++) {
                mt0 = fmaxf(mt0, fmaxf(p[j][0], p[j][1]));
                mt1 = fmaxf(mt1, fmaxf(p[j][2], p[j][3]));
            }
            mt0 = fmaxf(mt0, __shfl_xor_sync(0xffffffffu, mt0, 1));
            mt0 = fmaxf(mt0, __shfl_xor_sync(0xffffffffu, mt0, 2));
            mt1 = fmaxf(mt1, __shfl_xor_sync(0xffffffffu, mt1, 1));
            mt1 = fmaxf(mt1, __shfl_xor_sync(0xffffffffu, mt1, 2));

            float mnew0 = fmaxf(mrun0, mt0);
            float mnew1 = fmaxf(mrun1, mt1);
            float corr0, corr1;
            {
                float d0 = fmaxf(mrun0 - mnew0, -126.0f);
                float d1 = fmaxf(mrun1 - mnew1, -126.0f);
                asm("ex2.approx.f32 %0, %1;" : "=f"(corr0) : "f"(d0));
                asm("ex2.approx.f32 %0, %1;" : "=f"(corr1) : "f"(d1));
            }
            mrun0 = mnew0; mrun1 = mnew1;

            unsigned pf[8][2];
#pragma unroll
            for (int j = 0; j < 8; j++) {
                float y0 = fmaxf(p[j][0] - mnew0, YCLAMP);
                float y1 = fmaxf(p[j][1] - mnew0, YCLAMP);
                float y2 = fmaxf(p[j][2] - mnew1, YCLAMP);
                float y3 = fmaxf(p[j][3] - mnew1, YCLAMP);
                unsigned t0, t1;
                asm("cvt.rn.f16x2.f32 %0, %1, %2;" : "=r"(t0) : "f"(y1), "f"(y0));
                asm("cvt.rn.f16x2.f32 %0, %1, %2;" : "=r"(t1) : "f"(y3), "f"(y2));
                asm("ex2.approx.f16x2 %0, %0;" : "+r"(t0));
                asm("ex2.approx.f16x2 %0, %0;" : "+r"(t1));
                pf[j][0] = t0;
                pf[j][1] = t1;
                o[j][0] *= corr0; o[j][1] *= corr0;
                o[j][2] *= corr1; o[j][3] *= corr1;
            }

            float ltmp[4] = {0.0f, 0.0f, 0.0f, 0.0f};
            const unsigned ones2[2] = {0x3C003C00u, 0x3C003C00u};
#pragma unroll
            for (int kc = 0; kc < 4; kc++) {
                unsigned pa[4] = {pf[2 * kc][0], pf[2 * kc][1],
                                  pf[2 * kc + 1][0], pf[2 * kc + 1][1]};
                mma16816h(ltmp, pa, ones2);
#pragma unroll
                for (int j = 0; j < 8; j++) {
                    int bbase = (j * 8 + g) * STR + kc * 8 + tig;
                    unsigned bh[2] = {VHI[bbase], VHI[bbase + 4]};
                    unsigned bl[2] = {VLO[bbase], VLO[bbase + 4]};
                    mma16816h(o[j], pa, bh);
                    mma16816h(o[j], pa, bl);
                }
            }
            lrun0 = lrun0 * corr0 + ltmp[0];
            lrun1 = lrun1 * corr1 + ltmp[2];
        }

        __syncthreads();
        if (kt + 2 < nkt) {
            fillKV(kt & 1, c0 + 128);
            cp_commit();
        }
    }

    float inv0 = 1.0f / lrun0;
    float inv1 = 1.0f / lrun1;
#pragma unroll
    for (int j = 0; j < 8; j++) {
        int dh = j * 8 + 2 * tig;
        size_t r0 = ((size_t)b * SS + wrow + g) * DD + h * DH + dh;
        size_t r1 = ((size_t)b * SS + wrow + g + 8) * DD + h * DH + dh;
        unsigned h0, l0, h1, l1;
        split2h(o[j][0] * inv0, o[j][1] * inv0, h0, l0);
        split2h(o[j][2] * inv1, o[j][3] * inv1, h1, l1);
        *(unsigned*)(CtxHi + r0) = h0;
        *(unsigned*)(CtxLo + r0) = l0;
        *(unsigned*)(CtxHi + r1) = h1;
        *(unsigned*)(CtxLo + r1) = l1;
    }
}

// ---------------------------------------------------------------------------
// Launch
// ---------------------------------------------------------------------------
extern "C" void kernel_launch(void* const* d_in, const int* in_sizes, int n_in,
                              void* d_out, int out_size)
{
    const float* q  = (const float*)d_in[0];
    const float* k  = (const float*)d_in[1];
    const float* v  = (const float*)d_in[2];
    // d_in[3] = mask (causal; analytic)
    const float* wq = (const float*)d_in[4];
    const float* bq = (const float*)d_in[5];
    const float* wk = (const float*)d_in[6];
    const float* bk = (const float*)d_in[7];
    const float* wv = (const float*)d_in[8];
    const float* bv = (const float*)d_in[9];
    const float* wo = (const float*)d_in[10];
    const float* bo = (const float*)d_in[11];
    float* out = (float*)d_out;

    __half *actHi, *actLo, *wHi, *wLo;
    __half *Qhi, *Qlo, *Khi, *Klo, *Vhi, *Vlo;
    cudaGetSymbolAddress((void**)&actHi, g_ActHi);
    cudaGetSymbolAddress((void**)&actLo, g_ActLo);
    cudaGetSymbolAddress((void**)&wHi,  g_WHi);
    cudaGetSymbolAddress((void**)&wLo,  g_WLo);
    cudaGetSymbolAddress((void**)&Qhi, g_Qhi);
    cudaGetSymbolAddress((void**)&Qlo, g_Qlo);
    cudaGetSymbolAddress((void**)&Khi, g_Khi);
    cudaGetSymbolAddress((void**)&Klo, g_Klo);
    cudaGetSymbolAddress((void**)&Vhi, g_Vhi);
    cudaGetSymbolAddress((void**)&Vlo, g_Vlo);

    cudaFuncSetAttribute(flash_attn_tc, cudaFuncAttributeMaxDynamicSharedMemorySize,
                         FA_SMEM);
    cudaFuncSetAttribute(gemm_f16split<0>, cudaFuncAttributeMaxDynamicSharedMemorySize,
                         G_SMEM);
    cudaFuncSetAttribute(gemm_f16split<1>, cudaFuncAttributeMaxDynamicSharedMemorySize,
                         G_SMEM);
    cudaFuncSetAttribute(gemm_f16split<2>, cudaFuncAttributeMaxDynamicSharedMemorySize,
                         G_SMEM);

    const size_t AP = (size_t)MM * DD;   // activation plane
    const size_t WP = (size_t)DD * DD;   // weight plane

    dim3 sa(((MM * DD / 4) + 255) / 256, 3);
    dim3 sw(((DD * DD / 4) + 255) / 256, 4);
    dim3 gg(DD / GBN, MM / GBM);         // (8, 32)
    dim3 fg(SS / 128, HH, BB);           // (16, 16, 4)

    const float qscale = 0.125f * 1.44269504088896f;  // 1/sqrt(DH) * log2(e)

    // 0: activation splits (q,k,v -> planes 0,1,2)
    split_acts<<<sa, 256>>>(q, k, v, actHi, actLo);
    // 1: weight splits (wq,wk,wv,wo -> planes 0..3)
    split_wts<<<sw, 256>>>(wq, wk, wv, wo, wHi, wLo);
    // 2: Q projection (pre-scaled, log2 domain)
    gemm_f16split<1><<<gg, 512, G_SMEM>>>(actHi, actLo, wHi, wLo, bq, qscale,
                                          nullptr, Qhi, Qlo);
    // 3: K projection
    gemm_f16split<1><<<gg, 512, G_SMEM>>>(actHi + AP, actLo + AP, wHi + WP, wLo + WP,
                                          bk, 1.0f, nullptr, Khi, Klo);
    // 4: V projection -> transposed split [b][h][dh][s]
    gemm_f16split<2><<<gg, 512, G_SMEM>>>(actHi + 2 * AP, actLo + 2 * AP,
                                          wHi + 2 * WP, wLo + 2 * WP,
                                          bv, 1.0f, nullptr, Vhi, Vlo);
    // 5: attention -> split ctx into activation plane 0
    flash_attn_tc<<<fg, 256, FA_SMEM>>>(Qhi, Qlo, Khi, Klo, Vhi, Vlo, actHi, actLo);
    // 6: output projection (fp32)
    gemm_f16split<0><<<gg, 512, G_SMEM>>>(actHi, actLo, wHi + 3 * WP, wLo + 3 * WP,
                                          bo, 1.0f, out, nullptr, nullptr);
}